// round 10
// baseline (speedup 1.0000x reference)
#include <cuda_runtime.h>
#include <cstdint>
#include <cstddef>

#define D_MODEL 1024
#define NH      16
#define DH      64
#define BB      4
#define TT      2048
#define BT      (BB * TT)

__device__ float g_qkv[(size_t)BT * 3 * D_MODEL];   // [B*T, 3072]
__device__ float g_y  [(size_t)BT * D_MODEL];       // [B*T, 1024]

// ---------------------------------------------------------------------------
__device__ __forceinline__ uint32_t f2tf(float x) {
    uint32_t u;
    asm("cvt.rna.tf32.f32 %0, %1;" : "=r"(u) : "f"(x));
    return u;
}

__device__ __forceinline__ uint32_t tfr(uint32_t raw) {   // raw fp32 bits -> tf32 (rna)
    return f2tf(__uint_as_float(raw));
}

__device__ __forceinline__ void mma_tf32(float c[4], const uint32_t a[4],
                                         const uint32_t b[2]) {
    asm volatile(
        "mma.sync.aligned.m16n8k8.row.col.f32.tf32.tf32.f32 "
        "{%0,%1,%2,%3},{%4,%5,%6,%7},{%8,%9},{%0,%1,%2,%3};"
        : "+f"(c[0]), "+f"(c[1]), "+f"(c[2]), "+f"(c[3])
        : "r"(a[0]), "r"(a[1]), "r"(a[2]), "r"(a[3]), "r"(b[0]), "r"(b[1]));
}

__device__ __forceinline__ uint32_t smem_u32(const void* p) {
    uint32_t a;
    asm("{ .reg .u64 t; cvta.to.shared.u64 t, %1; cvt.u32.u64 %0, t; }"
        : "=r"(a) : "l"(p));
    return a;
}

__device__ __forceinline__ void cpa16(uint32_t dst, const void* src) {
    asm volatile("cp.async.ca.shared.global [%0], [%1], 16;"
                 :: "r"(dst), "l"(src) : "memory");
}

// ---------------------------------------------------------------------------
// TF32 GEMM (round-5 known-good): C[M,N] = A[M,K] * B[N,K]^T.
// 128x128 block, 8 warps (64x32 each), K-chunk 32.
// Coalesced LDG + XOR-swizzled fragment-order smem (conflict-free STS/LDS).
// ---------------------------------------------------------------------------
__global__ __launch_bounds__(256)
void gemm_tf32(const float* __restrict__ A, const float* __restrict__ Bw,
               float* __restrict__ C, int M, int N, int K) {
    __shared__ __align__(16) uint32_t As[8 * 4 * 4 * 32];
    __shared__ __align__(16) uint32_t Bs[16 * 4 * 2 * 32];

    const int tid    = threadIdx.x;
    const int lane   = tid & 31;
    const int wid    = tid >> 5;
    const int warp_m = wid >> 2;
    const int warp_n = wid & 3;
    const int m0     = blockIdx.y * 128;
    const int n0     = blockIdx.x * 128;

    float acc[4][4][4];
    #pragma unroll
    for (int i = 0; i < 4; i++)
        #pragma unroll
        for (int j = 0; j < 4; j++)
            #pragma unroll
            for (int r = 0; r < 4; r++) acc[i][j][r] = 0.f;

    for (int k0 = 0; k0 < K; k0 += 32) {
        #pragma unroll
        for (int it = 0; it < 4; it++) {
            int lin = tid + it * 256;
            int row = lin >> 3;
            int q   = lin & 7;
            float4 v = *(const float4*)&A[(size_t)(m0 + row) * K + k0 + q * 4];
            int off = ((((row >> 4) * 4 + (q >> 1)) * 4 + (((row >> 3) & 1) + 2 * (q & 1))) << 5)
                      + ((((row & 7) << 2)) ^ (q << 2));
            *(uint4*)&As[off] = make_uint4(f2tf(v.x), f2tf(v.y), f2tf(v.z), f2tf(v.w));
        }
        #pragma unroll
        for (int it = 0; it < 4; it++) {
            int lin = tid + it * 256;
            int row = lin >> 3;
            int q   = lin & 7;
            float4 v = *(const float4*)&Bw[(size_t)(n0 + row) * K + k0 + q * 4];
            int off = ((((row >> 3) * 4 + (q >> 1)) * 2 + (q & 1)) << 5)
                      + ((((row & 7) << 2)) ^ (q << 2));
            *(uint4*)&Bs[off] = make_uint4(f2tf(v.x), f2tf(v.y), f2tf(v.z), f2tf(v.w));
        }
        __syncthreads();

        #pragma unroll
        for (int ks = 0; ks < 4; ks++) {
            uint32_t af[4][4], bf[4][2];
            #pragma unroll
            for (int i = 0; i < 4; i++) {
                int base = ((warp_m * 4 + i) * 4 + ks) * 4 * 32;
                #pragma unroll
                for (int aidx = 0; aidx < 4; aidx++) {
                    int q = 2 * ks + (aidx >> 1);
                    af[i][aidx] = As[base + aidx * 32 + (lane ^ (q << 2))];
                }
            }
            #pragma unroll
            for (int j = 0; j < 4; j++) {
                int base = ((warp_n * 4 + j) * 4 + ks) * 2 * 32;
                #pragma unroll
                for (int p = 0; p < 2; p++) {
                    int q = 2 * ks + p;
                    bf[j][p] = Bs[base + p * 32 + (lane ^ (q << 2))];
                }
            }
            #pragma unroll
            for (int i = 0; i < 4; i++)
                #pragma unroll
                for (int j = 0; j < 4; j++)
                    mma_tf32(acc[i][j], af[i], bf[j]);
        }
        __syncthreads();
    }

    const int g = lane >> 2, t = lane & 3;
    #pragma unroll
    for (int i = 0; i < 4; i++) {
        int rbase = m0 + warp_m * 64 + i * 16 + g;
        #pragma unroll
        for (int j = 0; j < 4; j++) {
            int cbase = n0 + warp_n * 32 + j * 8 + t * 2;
            *(float2*)&C[(size_t)rbase * N + cbase] =
                make_float2(acc[i][j][0], acc[i][j][1]);
            *(float2*)&C[(size_t)(rbase + 8) * N + cbase] =
                make_float2(acc[i][j][2], acc[i][j][3]);
        }
    }
}

// ---------------------------------------------------------------------------
// Tensor-core flash attention v5 (tf32, mma.sync).
// cp.async.ca double-buffered K/V staging: tile j+1 streams into the alternate
// buffer while tile j computes; cvt.rna at fragment consume (bit-identical).
//   K buffer: fragment layout [kg_d 8][nt_key 8][plane 2][32] (raw fp32)
//   V buffer: row-major swizzled  word = key*64 + (d ^ ((key&7)<<3))
// Per buffer 32KB; 2 buffers = 64KB dynamic smem.
// ---------------------------------------------------------------------------
#define ATTN_SMEM 65536

__global__ __launch_bounds__(128, 3)
void attn_tc() {
    extern __shared__ __align__(16) uint32_t sm[];   // [2][8192]: K 4096 | V 4096

    const int tid  = threadIdx.x;
    const int lane = tid & 31;
    const int w    = tid >> 5;
    const int g    = lane >> 2;
    const int t    = lane & 3;
    const int qt   = (int)(gridDim.x - 1u - blockIdx.x);   // heavy first
    const int h    = blockIdx.y;
    const int b    = blockIdx.z;

    const size_t base = (size_t)b * TT * (3 * D_MODEL);
    const int    hcol = h * DH;
    const int    q0   = qt * 64 + w * 16;

    const uint32_t smaddr = smem_u32(sm);

    // staging coords (fixed per thread across iterations)
    // it-th: lin = tid + it*128; key = (lin&7)|((lin>>7)<<3); c = (lin>>3)&15

    // Q fragments, pre-scaled by 1/8 (exact)
    uint32_t qf[8][4];
    {
        const float* qA = g_qkv + base + (size_t)(q0 + g) * (3 * D_MODEL) + hcol;
        const float* qB = qA + (size_t)8 * (3 * D_MODEL);
        #pragma unroll
        for (int kg = 0; kg < 8; kg++) {
            qf[kg][0] = f2tf(0.125f * qA[kg * 8 + t]);
            qf[kg][1] = f2tf(0.125f * qB[kg * 8 + t]);
            qf[kg][2] = f2tf(0.125f * qA[kg * 8 + t + 4]);
            qf[kg][3] = f2tf(0.125f * qB[kg * 8 + t + 4]);
        }
    }

    // ---- stage tile 0 into buffer 0 ----
    {
        const float* kp = g_qkv + base + D_MODEL + hcol;
        #pragma unroll
        for (int it = 0; it < 8; it++) {
            int lin = tid + it * 128;
            int key = (lin & 7) | ((lin >> 7) << 3);
            int c   = (lin >> 3) & 15;
            const float* src = kp + (size_t)key * (3 * D_MODEL) + c * 4;
            int koff = (((((c >> 1) * 8 + (key >> 3)) * 2) + (c & 1)) << 5) + ((key & 7) << 2);
            cpa16(smaddr + koff * 4, src);
            int voff = key * 64 + ((c * 4) ^ ((key & 7) << 3));
            cpa16(smaddr + (4096 + voff) * 4, src + D_MODEL);
        }
        asm volatile("cp.async.commit_group;" ::: "memory");
    }

    float m0v = -1e30f, m1v = -1e30f, l0 = 0.f, l1 = 0.f;
    float o[8][4];
    #pragma unroll
    for (int nt = 0; nt < 8; nt++)
        #pragma unroll
        for (int e = 0; e < 4; e++) o[nt][e] = 0.f;

    const int src  = (lane & ~3) | (t >> 1);
    const int src2 = src + 2;

    for (int j = 0; j <= qt; j++) {
        // ---- issue next tile's cp.async before waiting on current ----
        if (j < qt) {
            const uint32_t nb = ((j + 1) & 1) * 8192 * 4;   // byte offset
            const float* kp = g_qkv + base + (size_t)((j + 1) * 64) * (3 * D_MODEL)
                              + D_MODEL + hcol;
            #pragma unroll
            for (int it = 0; it < 8; it++) {
                int lin = tid + it * 128;
                int key = (lin & 7) | ((lin >> 7) << 3);
                int c   = (lin >> 3) & 15;
                const float* srcp = kp + (size_t)key * (3 * D_MODEL) + c * 4;
                int koff = (((((c >> 1) * 8 + (key >> 3)) * 2) + (c & 1)) << 5) + ((key & 7) << 2);
                cpa16(smaddr + nb + koff * 4, srcp);
                int voff = key * 64 + ((c * 4) ^ ((key & 7) << 3));
                cpa16(smaddr + nb + (4096 + voff) * 4, srcp + D_MODEL);
            }
            asm volatile("cp.async.commit_group;" ::: "memory");
            asm volatile("cp.async.wait_group 1;" ::: "memory");
        } else {
            asm volatile("cp.async.wait_group 0;" ::: "memory");
        }
        __syncthreads();

        const uint32_t* Kb = sm + (j & 1) * 8192;
        const uint32_t* Vb = Kb + 4096;

        const bool diag = (j == qt);
        const int  lim  = diag ? (2 * w + 2) : 8;

        // ---- S = Q K^T (Q pre-scaled; cvt at consume) ----
        float s[8][4];
        #pragma unroll
        for (int nt = 0; nt < 8; nt++) {
            if (nt < lim) {
                #pragma unroll
                for (int e = 0; e < 4; e++) s[nt][e] = 0.f;
                #pragma unroll
                for (int kg = 0; kg < 8; kg++) {
                    int kb = ((kg * 8 + nt) * 2) << 5;
                    uint32_t bf[2] = {tfr(Kb[kb + lane]), tfr(Kb[kb + 32 + lane])};
                    mma_tf32(s[nt], qf[kg], bf);
                }
            }
        }

        // ---- causal mask (diagonal tile only) ----
        if (diag) {
            #pragma unroll
            for (int nt = 0; nt < 8; nt++) {
                if (nt < lim) {
                    #pragma unroll
                    for (int e = 0; e < 4; e++) {
                        int keyl = nt * 8 + 2 * t + (e & 1);
                        int rowl = w * 16 + g + ((e >> 1) << 3);
                        if (keyl > rowl) s[nt][e] = -1e30f;
                    }
                }
            }
        }

        // ---- online softmax ----
        float rm0 = -1e30f, rm1 = -1e30f;
        #pragma unroll
        for (int nt = 0; nt < 8; nt++) {
            if (nt < lim) {
                rm0 = fmaxf(rm0, fmaxf(s[nt][0], s[nt][1]));
                rm1 = fmaxf(rm1, fmaxf(s[nt][2], s[nt][3]));
            }
        }
        rm0 = fmaxf(rm0, __shfl_xor_sync(0xffffffffu, rm0, 1));
        rm0 = fmaxf(rm0, __shfl_xor_sync(0xffffffffu, rm0, 2));
        rm1 = fmaxf(rm1, __shfl_xor_sync(0xffffffffu, rm1, 1));
        rm1 = fmaxf(rm1, __shfl_xor_sync(0xffffffffu, rm1, 2));

        float mn0 = fmaxf(m0v, rm0), mn1 = fmaxf(m1v, rm1);
        float a0 = __expf(m0v - mn0), a1 = __expf(m1v - mn1);
        m0v = mn0; m1v = mn1;

        float rs0 = 0.f, rs1 = 0.f;
        #pragma unroll
        for (int nt = 0; nt < 8; nt++) {
            if (nt < lim) {
                s[nt][0] = __expf(s[nt][0] - mn0);
                s[nt][1] = __expf(s[nt][1] - mn0);
                s[nt][2] = __expf(s[nt][2] - mn1);
                s[nt][3] = __expf(s[nt][3] - mn1);
                rs0 += s[nt][0] + s[nt][1];
                rs1 += s[nt][2] + s[nt][3];
            }
        }
        rs0 += __shfl_xor_sync(0xffffffffu, rs0, 1);
        rs0 += __shfl_xor_sync(0xffffffffu, rs0, 2);
        rs1 += __shfl_xor_sync(0xffffffffu, rs1, 1);
        rs1 += __shfl_xor_sync(0xffffffffu, rs1, 2);
        l0 = l0 * a0 + rs0;
        l1 = l1 * a1 + rs1;

        #pragma unroll
        for (int nt = 0; nt < 8; nt++) {
            o[nt][0] *= a0; o[nt][1] *= a0;
            o[nt][2] *= a1; o[nt][3] *= a1;
        }

        // ---- PV: kg-outer, transient P fragment; V row-swizzled consume ----
        #pragma unroll
        for (int kg = 0; kg < 8; kg++) {
            if (kg < lim) {
                uint32_t c0 = f2tf(s[kg][0]), c1 = f2tf(s[kg][1]);
                uint32_t c2 = f2tf(s[kg][2]), c3 = f2tf(s[kg][3]);
                uint32_t u0 = __shfl_sync(0xffffffffu, c0, src);
                uint32_t u1 = __shfl_sync(0xffffffffu, c1, src);
                uint32_t u2 = __shfl_sync(0xffffffffu, c2, src);
                uint32_t u3 = __shfl_sync(0xffffffffu, c3, src);
                uint32_t v0 = __shfl_sync(0xffffffffu, c0, src2);
                uint32_t v1 = __shfl_sync(0xffffffffu, c1, src2);
                uint32_t v2 = __shfl_sync(0xffffffffu, c2, src2);
                uint32_t v3 = __shfl_sync(0xffffffffu, c3, src2);
                bool odd = (t & 1);
                uint32_t p[4];
                p[0] = odd ? u1 : u0;
                p[1] = odd ? u3 : u2;
                p[2] = odd ? v1 : v0;
                p[3] = odd ? v3 : v2;

                const int r0w = (8 * kg + t) * 64;          // V row for b0
                const int r1w = (8 * kg + t + 4) * 64;      // V row for b1
                const int sx0 = t << 3;                     // swizzle for b0
                #pragma unroll
                for (int nt = 0; nt < 8; nt++) {
                    int col = 8 * nt + g;
                    uint32_t bf[2] = {tfr(Vb[r0w + (col ^ sx0)]),
                                      tfr(Vb[r1w + (col ^ sx0 ^ 32)])};
                    mma_tf32(o[nt], p, bf);
                }
            }
        }
        __syncthreads();   // done reading buf[j&1] before it's restaged
    }

    float inv0 = 1.f / l0, inv1 = 1.f / l1;
    size_t r0 = (size_t)(b * TT + q0 + g) * D_MODEL + hcol;
    size_t r1 = (size_t)(b * TT + q0 + g + 8) * D_MODEL + hcol;
    #pragma unroll
    for (int nt = 0; nt < 8; nt++) {
        int cb = nt * 8 + 2 * t;
        *(float2*)&g_y[r0 + cb] = make_float2(o[nt][0] * inv0, o[nt][1] * inv0);
        *(float2*)&g_y[r1 + cb] = make_float2(o[nt][2] * inv1, o[nt][3] * inv1);
    }
}

// ---------------------------------------------------------------------------
extern "C" void kernel_launch(void* const* d_in, const int* in_sizes, int n_in,
                              void* d_out, int out_size) {
    const float* x      = (const float*)d_in[0];
    const float* w_qkv  = (const float*)d_in[1];
    const float* w_proj = (const float*)d_in[2];
    float*       out    = (float*)d_out;

    float *qkv_ptr = nullptr, *y_ptr = nullptr;
    cudaGetSymbolAddress((void**)&qkv_ptr, g_qkv);
    cudaGetSymbolAddress((void**)&y_ptr,   g_y);

    cudaFuncSetAttribute(attn_tc, cudaFuncAttributeMaxDynamicSharedMemorySize, ATTN_SMEM);

    gemm_tf32<<<dim3(3 * D_MODEL / 128, BT / 128), 256>>>(x, w_qkv, qkv_ptr,
                                                          BT, 3 * D_MODEL, D_MODEL);

    attn_tc<<<dim3(TT / 64, NH, BB), 128, ATTN_SMEM>>>();

    gemm_tf32<<<dim3(D_MODEL / 128, BT / 128), 256>>>(y_ptr, w_proj, out,
                                                      BT, D_MODEL, D_MODEL);
}

// round 11
// speedup vs baseline: 1.0333x; 1.0333x over previous
#include <cuda_runtime.h>
#include <cstdint>
#include <cstddef>

#define D_MODEL 1024
#define NH      16
#define DH      64
#define BB      4
#define TT      2048
#define BT      (BB * TT)

__device__ float g_qkv[(size_t)BT * 3 * D_MODEL];   // [B*T, 3072]
__device__ float g_y  [(size_t)BT * D_MODEL];       // [B*T, 1024]

// ---------------------------------------------------------------------------
__device__ __forceinline__ uint32_t f2tf(float x) {
    uint32_t u;
    asm("cvt.rna.tf32.f32 %0, %1;" : "=r"(u) : "f"(x));
    return u;
}

__device__ __forceinline__ void mma_tf32(float c[4], const uint32_t a[4],
                                         const uint32_t b[2]) {
    asm volatile(
        "mma.sync.aligned.m16n8k8.row.col.f32.tf32.tf32.f32 "
        "{%0,%1,%2,%3},{%4,%5,%6,%7},{%8,%9},{%0,%1,%2,%3};"
        : "+f"(c[0]), "+f"(c[1]), "+f"(c[2]), "+f"(c[3])
        : "r"(a[0]), "r"(a[1]), "r"(a[2]), "r"(a[3]), "r"(b[0]), "r"(b[1]));
}

// ---------------------------------------------------------------------------
// TF32 GEMM (round-5 known-good): C[M,N] = A[M,K] * B[N,K]^T.
// 128x128 block, 8 warps (64x32 each), K-chunk 32.
// ---------------------------------------------------------------------------
__global__ __launch_bounds__(256)
void gemm_tf32(const float* __restrict__ A, const float* __restrict__ Bw,
               float* __restrict__ C, int M, int N, int K) {
    __shared__ __align__(16) uint32_t As[8 * 4 * 4 * 32];
    __shared__ __align__(16) uint32_t Bs[16 * 4 * 2 * 32];

    const int tid    = threadIdx.x;
    const int lane   = tid & 31;
    const int wid    = tid >> 5;
    const int warp_m = wid >> 2;
    const int warp_n = wid & 3;
    const int m0     = blockIdx.y * 128;
    const int n0     = blockIdx.x * 128;

    float acc[4][4][4];
    #pragma unroll
    for (int i = 0; i < 4; i++)
        #pragma unroll
        for (int j = 0; j < 4; j++)
            #pragma unroll
            for (int r = 0; r < 4; r++) acc[i][j][r] = 0.f;

    for (int k0 = 0; k0 < K; k0 += 32) {
        #pragma unroll
        for (int it = 0; it < 4; it++) {
            int lin = tid + it * 256;
            int row = lin >> 3;
            int q   = lin & 7;
            float4 v = *(const float4*)&A[(size_t)(m0 + row) * K + k0 + q * 4];
            int off = ((((row >> 4) * 4 + (q >> 1)) * 4 + (((row >> 3) & 1) + 2 * (q & 1))) << 5)
                      + ((((row & 7) << 2)) ^ (q << 2));
            *(uint4*)&As[off] = make_uint4(f2tf(v.x), f2tf(v.y), f2tf(v.z), f2tf(v.w));
        }
        #pragma unroll
        for (int it = 0; it < 4; it++) {
            int lin = tid + it * 256;
            int row = lin >> 3;
            int q   = lin & 7;
            float4 v = *(const float4*)&Bw[(size_t)(n0 + row) * K + k0 + q * 4];
            int off = ((((row >> 3) * 4 + (q >> 1)) * 2 + (q & 1)) << 5)
                      + ((((row & 7) << 2)) ^ (q << 2));
            *(uint4*)&Bs[off] = make_uint4(f2tf(v.x), f2tf(v.y), f2tf(v.z), f2tf(v.w));
        }
        __syncthreads();

        #pragma unroll
        for (int ks = 0; ks < 4; ks++) {
            uint32_t af[4][4], bf[4][2];
            #pragma unroll
            for (int i = 0; i < 4; i++) {
                int base = ((warp_m * 4 + i) * 4 + ks) * 4 * 32;
                #pragma unroll
                for (int aidx = 0; aidx < 4; aidx++) {
                    int q = 2 * ks + (aidx >> 1);
                    af[i][aidx] = As[base + aidx * 32 + (lane ^ (q << 2))];
                }
            }
            #pragma unroll
            for (int j = 0; j < 4; j++) {
                int base = ((warp_n * 4 + j) * 4 + ks) * 2 * 32;
                #pragma unroll
                for (int p = 0; p < 2; p++) {
                    int q = 2 * ks + p;
                    bf[j][p] = Bs[base + p * 32 + (lane ^ (q << 2))];
                }
            }
            #pragma unroll
            for (int i = 0; i < 4; i++)
                #pragma unroll
                for (int j = 0; j < 4; j++)
                    mma_tf32(acc[i][j], af[i], bf[j]);
        }
        __syncthreads();
    }

    const int g = lane >> 2, t = lane & 3;
    #pragma unroll
    for (int i = 0; i < 4; i++) {
        int rbase = m0 + warp_m * 64 + i * 16 + g;
        #pragma unroll
        for (int j = 0; j < 4; j++) {
            int cbase = n0 + warp_n * 32 + j * 8 + t * 2;
            *(float2*)&C[(size_t)rbase * N + cbase] =
                make_float2(acc[i][j][0], acc[i][j][1]);
            *(float2*)&C[(size_t)(rbase + 8) * N + cbase] =
                make_float2(acc[i][j][2], acc[i][j][3]);
        }
    }
}

// ---------------------------------------------------------------------------
// Tensor-core flash attention v6 (tf32, mma.sync).
// 128-KEY TILES: softmax rounds / shfl trees / transposes / syncs run half
// as often per key. Single 64KB dynamic smem buffer:
//   Kf (32KB): fragment layout [kg_d 8][nt_key 16][plane 2][32]
//   Vf (32KB): row-major swizzled  word = key*64 + (4c ^ ((key&7)<<3))
// Staging split into two loops with different lane maps so both K and V
// STS.128 are bank-conflict-free.
// ---------------------------------------------------------------------------
#define ATTN_SMEM 65536

__global__ __launch_bounds__(128, 3)
void attn_tc() {
    extern __shared__ __align__(16) uint32_t sm[];   // Kf 8192 | Vf 8192 words

    const int tid  = threadIdx.x;
    const int lane = tid & 31;
    const int w    = tid >> 5;
    const int g    = lane >> 2;
    const int t    = lane & 3;
    const int qt   = (int)(gridDim.x - 1u - blockIdx.x);   // heavy first
    const int h    = blockIdx.y;
    const int b    = blockIdx.z;

    const size_t base = (size_t)b * TT * (3 * D_MODEL);
    const int    hcol = h * DH;
    const int    q0   = qt * 64 + w * 16;

    uint32_t* Kf = sm;
    uint32_t* Vf = sm + 8192;

    // Q fragments, pre-scaled by 1/8 (exact power of 2)
    uint32_t qf[8][4];
    {
        const float* qA = g_qkv + base + (size_t)(q0 + g) * (3 * D_MODEL) + hcol;
        const float* qB = qA + (size_t)8 * (3 * D_MODEL);
        #pragma unroll
        for (int kg = 0; kg < 8; kg++) {
            qf[kg][0] = f2tf(0.125f * qA[kg * 8 + t]);
            qf[kg][1] = f2tf(0.125f * qB[kg * 8 + t]);
            qf[kg][2] = f2tf(0.125f * qA[kg * 8 + t + 4]);
            qf[kg][3] = f2tf(0.125f * qB[kg * 8 + t + 4]);
        }
    }

    float m0v = -1e30f, m1v = -1e30f, l0 = 0.f, l1 = 0.f;
    float o[8][4];
    #pragma unroll
    for (int nt = 0; nt < 8; nt++)
        #pragma unroll
        for (int e = 0; e < 4; e++) o[nt][e] = 0.f;

    const int src  = (lane & ~3) | (t >> 1);
    const int src2 = src + 2;

    const int nT = (qt + 2) >> 1;       // number of 128-key tiles
    for (int j = 0; j < nT; j++) {
        __syncthreads();
        const float* kp = g_qkv + base + (size_t)(j * 128) * (3 * D_MODEL)
                          + D_MODEL + hcol;
        // ---- stage K: key=(lin&7)|((lin>>7)<<3), c=(lin>>3)&15 ----
        #pragma unroll
        for (int it = 0; it < 16; it++) {
            int lin = tid + it * 128;
            int key = (lin & 7) | ((lin >> 7) << 3);
            int c   = (lin >> 3) & 15;
            float4 v = *(const float4*)(kp + (size_t)key * (3 * D_MODEL) + c * 4);
            int koff = (((((c >> 1) * 16 + (key >> 3)) * 2) + (c & 1)) << 5) + ((key & 7) << 2);
            *(uint4*)&Kf[koff] = make_uint4(f2tf(v.x), f2tf(v.y), f2tf(v.z), f2tf(v.w));
        }
        // ---- stage V: key=lin>>4, c=lin&15 (row-contiguous, bank-clean) ----
        #pragma unroll
        for (int it = 0; it < 16; it++) {
            int lin = tid + it * 128;
            int key = lin >> 4;
            int c   = lin & 15;
            float4 v = *(const float4*)(kp + (size_t)key * (3 * D_MODEL) + D_MODEL + c * 4);
            int voff = key * 64 + ((c * 4) ^ ((key & 7) << 3));
            *(uint4*)&Vf[voff] = make_uint4(f2tf(v.x), f2tf(v.y), f2tf(v.z), f2tf(v.w));
        }
        __syncthreads();

        const int off = q0 - j * 128;                 // warp rows off..off+15
        const int rel = off + 15;
        int lim = (rel >> 3) + 1;
        if (lim > 16) lim = 16;
        const bool needMask = (8 * lim - 1 > off);

        // ---- S = Q K^T (Q pre-scaled) ----
        float s[16][4];
        #pragma unroll
        for (int nt = 0; nt < 16; nt++) {
            if (nt < lim) {
                #pragma unroll
                for (int e = 0; e < 4; e++) s[nt][e] = 0.f;
                #pragma unroll
                for (int kg = 0; kg < 8; kg++) {
                    int kb = ((kg * 16 + nt) * 2) << 5;
                    uint32_t bf[2] = {Kf[kb + lane], Kf[kb + 32 + lane]};
                    mma_tf32(s[nt], qf[kg], bf);
                }
            }
        }

        // ---- causal mask ----
        if (needMask) {
            #pragma unroll
            for (int nt = 0; nt < 16; nt++) {
                if (nt < lim) {
                    #pragma unroll
                    for (int e = 0; e < 4; e++) {
                        int keyl = nt * 8 + 2 * t + (e & 1);
                        int rowl = off + g + ((e >> 1) << 3);
                        if (keyl > rowl) s[nt][e] = -1e30f;
                    }
                }
            }
        }

        // ---- online softmax ----
        float rm0 = -1e30f, rm1 = -1e30f;
        #pragma unroll
        for (int nt = 0; nt < 16; nt++) {
            if (nt < lim) {
                rm0 = fmaxf(rm0, fmaxf(s[nt][0], s[nt][1]));
                rm1 = fmaxf(rm1, fmaxf(s[nt][2], s[nt][3]));
            }
        }
        rm0 = fmaxf(rm0, __shfl_xor_sync(0xffffffffu, rm0, 1));
        rm0 = fmaxf(rm0, __shfl_xor_sync(0xffffffffu, rm0, 2));
        rm1 = fmaxf(rm1, __shfl_xor_sync(0xffffffffu, rm1, 1));
        rm1 = fmaxf(rm1, __shfl_xor_sync(0xffffffffu, rm1, 2));

        float mn0 = fmaxf(m0v, rm0), mn1 = fmaxf(m1v, rm1);
        float a0 = __expf(m0v - mn0), a1 = __expf(m1v - mn1);
        m0v = mn0; m1v = mn1;

        float rs0 = 0.f, rs1 = 0.f;
        #pragma unroll
        for (int nt = 0; nt < 16; nt++) {
            if (nt < lim) {
                s[nt][0] = __expf(s[nt][0] - mn0);
                s[nt][1] = __expf(s[nt][1] - mn0);
                s[nt][2] = __expf(s[nt][2] - mn1);
                s[nt][3] = __expf(s[nt][3] - mn1);
                rs0 += s[nt][0] + s[nt][1];
                rs1 += s[nt][2] + s[nt][3];
            }
        }
        rs0 += __shfl_xor_sync(0xffffffffu, rs0, 1);
        rs0 += __shfl_xor_sync(0xffffffffu, rs0, 2);
        rs1 += __shfl_xor_sync(0xffffffffu, rs1, 1);
        rs1 += __shfl_xor_sync(0xffffffffu, rs1, 2);
        l0 = l0 * a0 + rs0;
        l1 = l1 * a1 + rs1;

        #pragma unroll
        for (int nt = 0; nt < 8; nt++) {
            o[nt][0] *= a0; o[nt][1] *= a0;
            o[nt][2] *= a1; o[nt][3] *= a1;
        }

        // ---- PV: kg-outer (16 key groups), transient P fragment ----
        #pragma unroll
        for (int kg = 0; kg < 16; kg++) {
            if (kg < lim) {
                uint32_t c0 = f2tf(s[kg][0]), c1 = f2tf(s[kg][1]);
                uint32_t c2 = f2tf(s[kg][2]), c3 = f2tf(s[kg][3]);
                uint32_t u0 = __shfl_sync(0xffffffffu, c0, src);
                uint32_t u1 = __shfl_sync(0xffffffffu, c1, src);
                uint32_t u2 = __shfl_sync(0xffffffffu, c2, src);
                uint32_t u3 = __shfl_sync(0xffffffffu, c3, src);
                uint32_t v0 = __shfl_sync(0xffffffffu, c0, src2);
                uint32_t v1 = __shfl_sync(0xffffffffu, c1, src2);
                uint32_t v2 = __shfl_sync(0xffffffffu, c2, src2);
                uint32_t v3 = __shfl_sync(0xffffffffu, c3, src2);
                bool odd = (t & 1);
                uint32_t p[4];
                p[0] = odd ? u1 : u0;
                p[1] = odd ? u3 : u2;
                p[2] = odd ? v1 : v0;
                p[3] = odd ? v3 : v2;

                const int r0w = (8 * kg + t) * 64;
                const int r1w = (8 * kg + t + 4) * 64;
                const int sx0 = t << 3;
                #pragma unroll
                for (int nt = 0; nt < 8; nt++) {
                    int col = 8 * nt + g;
                    uint32_t bf[2] = {Vf[r0w + (col ^ sx0)],
                                      Vf[r1w + (col ^ sx0 ^ 32)]};
                    mma_tf32(o[nt], p, bf);
                }
            }
        }
    }

    float inv0 = 1.f / l0, inv1 = 1.f / l1;
    size_t r0 = (size_t)(b * TT + q0 + g) * D_MODEL + hcol;
    size_t r1 = (size_t)(b * TT + q0 + g + 8) * D_MODEL + hcol;
    #pragma unroll
    for (int nt = 0; nt < 8; nt++) {
        int cb = nt * 8 + 2 * t;
        *(float2*)&g_y[r0 + cb] = make_float2(o[nt][0] * inv0, o[nt][1] * inv0);
        *(float2*)&g_y[r1 + cb] = make_float2(o[nt][2] * inv1, o[nt][3] * inv1);
    }
}

// ---------------------------------------------------------------------------
extern "C" void kernel_launch(void* const* d_in, const int* in_sizes, int n_in,
                              void* d_out, int out_size) {
    const float* x      = (const float*)d_in[0];
    const float* w_qkv  = (const float*)d_in[1];
    const float* w_proj = (const float*)d_in[2];
    float*       out    = (float*)d_out;

    float *qkv_ptr = nullptr, *y_ptr = nullptr;
    cudaGetSymbolAddress((void**)&qkv_ptr, g_qkv);
    cudaGetSymbolAddress((void**)&y_ptr,   g_y);

    cudaFuncSetAttribute(attn_tc, cudaFuncAttributeMaxDynamicSharedMemorySize, ATTN_SMEM);

    gemm_tf32<<<dim3(3 * D_MODEL / 128, BT / 128), 256>>>(x, w_qkv, qkv_ptr,
                                                          BT, 3 * D_MODEL, D_MODEL);

    attn_tc<<<dim3(TT / 64, NH, BB), 128, ATTN_SMEM>>>();

    gemm_tf32<<<dim3(D_MODEL / 128, BT / 128), 256>>>(y_ptr, w_proj, out,
                                                      BT, D_MODEL, D_MODEL);
}

// round 12
// speedup vs baseline: 1.4416x; 1.3952x over previous
#include <cuda_runtime.h>
#include <cuda_fp16.h>
#include <cstdint>
#include <cstddef>

#define D_MODEL 1024
#define NH      16
#define DH      64
#define BB      4
#define TT      2048
#define BT      (BB * TT)

__device__ float g_qkv[(size_t)BT * 3 * D_MODEL];   // [B*T, 3072]
__device__ float g_y  [(size_t)BT * D_MODEL];       // [B*T, 1024]

// ---------------------------------------------------------------------------
__device__ __forceinline__ uint32_t pk(float a, float b) {
    __half2 h = __floats2half2_rn(a, b);
    return *(uint32_t*)&h;
}

__device__ __forceinline__ void mma_fp16(float c[4], const uint32_t a[4],
                                         const uint32_t b[2]) {
    asm volatile(
        "mma.sync.aligned.m16n8k16.row.col.f32.f16.f16.f32 "
        "{%0,%1,%2,%3},{%4,%5,%6,%7},{%8,%9},{%0,%1,%2,%3};"
        : "+f"(c[0]), "+f"(c[1]), "+f"(c[2]), "+f"(c[3])
        : "r"(a[0]), "r"(a[1]), "r"(a[2]), "r"(a[3]), "r"(b[0]), "r"(b[1]));
}

// ---------------------------------------------------------------------------
// FP16 GEMM: C[M,N] = A[M,K] * B[N,K]^T.  fp32 accumulate.
// 128x128 block, 8 warps (warp tile 64x32), K-chunk 32 (= 2 ksteps of 16).
// Smem planes hold packed f16x2 words in fragment order with XOR swizzle:
//   As: [mtile 8][ks 2][aidx 4][pos 32]   Bs: [ntile 16][ks 2][bh 2][pos 32]
//   store: pos = (4*(row&7) + 2*(q&1) + j) ^ (4*q)      (q = float4 index 0..7)
//   consume: pos = (4*g + t) ^ (4*(4*ks + 2*hi + ((t>>1)&1)))
// Both sides proven conflict-free (store: groups (row&7)^q distinct; consume:
// bijection on 32 lanes).
// ---------------------------------------------------------------------------
__global__ __launch_bounds__(256)
void gemm_fp16(const float* __restrict__ A, const float* __restrict__ Bw,
               float* __restrict__ C, int M, int N, int K) {
    __shared__ __align__(16) uint32_t As[8 * 2 * 4 * 32];   // 8 KB
    __shared__ __align__(16) uint32_t Bs[16 * 2 * 2 * 32];  // 8 KB

    const int tid    = threadIdx.x;
    const int lane   = tid & 31;
    const int wid    = tid >> 5;
    const int warp_m = wid >> 2;
    const int warp_n = wid & 3;
    const int m0     = blockIdx.y * 128;
    const int n0     = blockIdx.x * 128;
    const int g      = lane >> 2;
    const int t      = lane & 3;

    float acc[4][4][4];
    #pragma unroll
    for (int i = 0; i < 4; i++)
        #pragma unroll
        for (int j = 0; j < 4; j++)
            #pragma unroll
            for (int r = 0; r < 4; r++) acc[i][j][r] = 0.f;

    for (int k0 = 0; k0 < K; k0 += 32) {
        // ---- stage A (coalesced LDG.128 -> pack -> swizzled STS.64) ----
        #pragma unroll
        for (int it = 0; it < 4; it++) {
            int lin = tid + it * 256;
            int row = lin >> 3;
            int q   = lin & 7;
            float4 v = *(const float4*)&A[(size_t)(m0 + row) * K + k0 + q * 4];
            int plane = ((row >> 4) * 2 + (q >> 2)) * 4 + ((row >> 3) & 1) + 2 * ((q >> 1) & 1);
            int pos0  = ((4 * (row & 7) + 2 * (q & 1))) ^ (4 * q);
            uint2 w = make_uint2(pk(v.x, v.y), pk(v.z, v.w));
            *(uint2*)&As[plane * 32 + pos0] = w;
        }
        // ---- stage B ----
        #pragma unroll
        for (int it = 0; it < 4; it++) {
            int lin = tid + it * 256;
            int row = lin >> 3;
            int q   = lin & 7;
            float4 v = *(const float4*)&Bw[(size_t)(n0 + row) * K + k0 + q * 4];
            int plane = ((row >> 3) * 2 + (q >> 2)) * 2 + ((q >> 1) & 1);
            int pos0  = ((4 * (row & 7) + 2 * (q & 1))) ^ (4 * q);
            uint2 w = make_uint2(pk(v.x, v.y), pk(v.z, v.w));
            *(uint2*)&Bs[plane * 32 + pos0] = w;
        }
        __syncthreads();

        #pragma unroll
        for (int ks = 0; ks < 2; ks++) {
            const int posLo = (4 * g + t) ^ (4 * (4 * ks + ((t >> 1) & 1)));       // hi=0
            const int posHi = (4 * g + t) ^ (4 * (4 * ks + 2 + ((t >> 1) & 1)));   // hi=1
            uint32_t af[4][4], bf[4][2];
            #pragma unroll
            for (int i = 0; i < 4; i++) {
                int base = (((warp_m * 4 + i) * 2 + ks) * 4) * 32;
                af[i][0] = As[base + posLo];
                af[i][1] = As[base + 32 + posLo];
                af[i][2] = As[base + 64 + posHi];
                af[i][3] = As[base + 96 + posHi];
            }
            #pragma unroll
            for (int j = 0; j < 4; j++) {
                int base = (((warp_n * 4 + j) * 2 + ks) * 2) * 32;
                bf[j][0] = Bs[base + posLo];
                bf[j][1] = Bs[base + 32 + posHi];
            }
            #pragma unroll
            for (int i = 0; i < 4; i++)
                #pragma unroll
                for (int j = 0; j < 4; j++)
                    mma_fp16(acc[i][j], af[i], bf[j]);
        }
        __syncthreads();
    }

    #pragma unroll
    for (int i = 0; i < 4; i++) {
        int rbase = m0 + warp_m * 64 + i * 16 + g;
        #pragma unroll
        for (int j = 0; j < 4; j++) {
            int cbase = n0 + warp_n * 32 + j * 8 + t * 2;
            *(float2*)&C[(size_t)rbase * N + cbase] =
                make_float2(acc[i][j][0], acc[i][j][1]);
            *(float2*)&C[(size_t)(rbase + 8) * N + cbase] =
                make_float2(acc[i][j][2], acc[i][j][3]);
        }
    }
}

// ---------------------------------------------------------------------------
// FP16 tensor-core flash attention. 4 warps x 16 q, 64-key tiles.
// fp16 k=16 MMAs: S gets d in 4 ksteps; PV gets keys in 4 groups of 16.
// P A-fragments = packed C-layout pairs (NO transpose shuffles).
//   Ks: [nt 8][ks 4][kh 2][pos 32]  pos = 4*(key&7) + (dp&3)  (no swizzle needed)
//   Vs: [kpair 32][64]   word(kp,d) at kp*64 + (d ^ 8*(kp&3))  (transposed pairs)
// ---------------------------------------------------------------------------
__global__ __launch_bounds__(128)
void attn_fp16() {
    __shared__ __align__(16) uint32_t Ks[8 * 4 * 2 * 32];   // 8 KB
    __shared__ __align__(16) uint32_t Vs[32 * 64];          // 8 KB

    const int tid  = threadIdx.x;
    const int lane = tid & 31;
    const int w    = tid >> 5;
    const int g    = lane >> 2;
    const int t    = lane & 3;
    const int qt   = (int)(gridDim.x - 1u - blockIdx.x);
    const int h    = blockIdx.y;
    const int b    = blockIdx.z;

    const size_t base = (size_t)b * TT * (3 * D_MODEL);
    const int    hcol = h * DH;
    const int    q0   = qt * 64 + w * 16;

    // Q fragments (pre-scaled by 1/8, exact), packed fp16: qf[ks][0..3]
    uint32_t qf[4][4];
    {
        const float* qA = g_qkv + base + (size_t)(q0 + g) * (3 * D_MODEL) + hcol;
        const float* qB = qA + (size_t)8 * (3 * D_MODEL);
        #pragma unroll
        for (int ks = 0; ks < 4; ks++) {
            int d = 16 * ks + 2 * t;
            qf[ks][0] = pk(0.125f * qA[d],     0.125f * qA[d + 1]);
            qf[ks][1] = pk(0.125f * qB[d],     0.125f * qB[d + 1]);
            qf[ks][2] = pk(0.125f * qA[d + 8], 0.125f * qA[d + 9]);
            qf[ks][3] = pk(0.125f * qB[d + 8], 0.125f * qB[d + 9]);
        }
    }

    float m0v = -1e30f, m1v = -1e30f, l0 = 0.f, l1 = 0.f;
    float o[8][4];
    #pragma unroll
    for (int nt = 0; nt < 8; nt++)
        #pragma unroll
        for (int e = 0; e < 4; e++) o[nt][e] = 0.f;

    for (int j = 0; j <= qt; j++) {
        __syncthreads();
        const float* kp0 = g_qkv + base + (size_t)(j * 64) * (3 * D_MODEL)
                           + D_MODEL + hcol;
        // ---- stage K: 8 it, key = (tid&7)+8*it, c = tid>>3 (0..15) ----
        #pragma unroll
        for (int it = 0; it < 8; it++) {
            int key = (tid & 7) + 8 * it;
            int c   = tid >> 3;
            float4 v = *(const float4*)(kp0 + (size_t)key * (3 * D_MODEL) + c * 4);
            int idx = ((((key >> 3) * 4 + (c >> 2)) * 2 + ((c >> 1) & 1)) << 5)
                      + 4 * (key & 7) + 2 * (c & 1);
            *(uint2*)&Ks[idx] = make_uint2(pk(v.x, v.y), pk(v.z, v.w));
        }
        // ---- stage V transposed pairs: 4 it, kp = (tid>>4)+8*it, c = tid&15 ----
        #pragma unroll
        for (int it = 0; it < 4; it++) {
            int kpair = (tid >> 4) + 8 * it;
            int c     = tid & 15;
            const float* va = kp0 + (size_t)(2 * kpair) * (3 * D_MODEL) + D_MODEL + c * 4;
            const float* vb = va + 3 * D_MODEL;
            float4 a4 = *(const float4*)va;
            float4 b4 = *(const float4*)vb;
            uint4 wv = make_uint4(pk(a4.x, b4.x), pk(a4.y, b4.y),
                                  pk(a4.z, b4.z), pk(a4.w, b4.w));
            *(uint4*)&Vs[kpair * 64 + ((4 * c) ^ (8 * (kpair & 3)))] = wv;
        }
        __syncthreads();

        const bool diag = (j == qt);
        const int  lim  = diag ? (2 * w + 2) : 8;     // always even

        // ---- S = Q K^T ----
        float s[8][4];
        #pragma unroll
        for (int nt = 0; nt < 8; nt++) {
            if (nt < lim) {
                #pragma unroll
                for (int e = 0; e < 4; e++) s[nt][e] = 0.f;
                #pragma unroll
                for (int ks = 0; ks < 4; ks++) {
                    int kb = ((nt * 4 + ks) * 2) << 5;
                    int pos = 4 * g + t;
                    uint32_t bf[2] = {Ks[kb + pos], Ks[kb + 32 + pos]};
                    mma_fp16(s[nt], qf[ks], bf);
                }
            }
        }

        // ---- causal mask (diagonal tile only) ----
        if (diag) {
            #pragma unroll
            for (int nt = 0; nt < 8; nt++) {
                if (nt < lim) {
                    #pragma unroll
                    for (int e = 0; e < 4; e++) {
                        int keyl = nt * 8 + 2 * t + (e & 1);
                        int rowl = w * 16 + g + ((e >> 1) << 3);
                        if (keyl > rowl) s[nt][e] = -1e30f;
                    }
                }
            }
        }

        // ---- online softmax ----
        float rm0 = -1e30f, rm1 = -1e30f;
        #pragma unroll
        for (int nt = 0; nt < 8; nt++) {
            if (nt < lim) {
                rm0 = fmaxf(rm0, fmaxf(s[nt][0], s[nt][1]));
                rm1 = fmaxf(rm1, fmaxf(s[nt][2], s[nt][3]));
            }
        }
        rm0 = fmaxf(rm0, __shfl_xor_sync(0xffffffffu, rm0, 1));
        rm0 = fmaxf(rm0, __shfl_xor_sync(0xffffffffu, rm0, 2));
        rm1 = fmaxf(rm1, __shfl_xor_sync(0xffffffffu, rm1, 1));
        rm1 = fmaxf(rm1, __shfl_xor_sync(0xffffffffu, rm1, 2));

        float mn0 = fmaxf(m0v, rm0), mn1 = fmaxf(m1v, rm1);
        float a0 = __expf(m0v - mn0), a1 = __expf(m1v - mn1);
        m0v = mn0; m1v = mn1;

        float rs0 = 0.f, rs1 = 0.f;
        #pragma unroll
        for (int nt = 0; nt < 8; nt++) {
            if (nt < lim) {
                s[nt][0] = __expf(s[nt][0] - mn0);
                s[nt][1] = __expf(s[nt][1] - mn0);
                s[nt][2] = __expf(s[nt][2] - mn1);
                s[nt][3] = __expf(s[nt][3] - mn1);
                rs0 += s[nt][0] + s[nt][1];
                rs1 += s[nt][2] + s[nt][3];
            }
        }
        rs0 += __shfl_xor_sync(0xffffffffu, rs0, 1);
        rs0 += __shfl_xor_sync(0xffffffffu, rs0, 2);
        rs1 += __shfl_xor_sync(0xffffffffu, rs1, 1);
        rs1 += __shfl_xor_sync(0xffffffffu, rs1, 2);
        l0 = l0 * a0 + rs0;
        l1 = l1 * a1 + rs1;

        #pragma unroll
        for (int nt = 0; nt < 8; nt++) {
            o[nt][0] *= a0; o[nt][1] *= a0;
            o[nt][2] *= a1; o[nt][3] *= a1;
        }

        // ---- PV: P fragments = packed C-layout pairs (no shuffles) ----
        const int limKK = lim >> 1;
        #pragma unroll
        for (int kk = 0; kk < 4; kk++) {
            if (kk < limKK) {
                uint32_t pA[4];
                pA[0] = pk(s[2 * kk][0],     s[2 * kk][1]);
                pA[1] = pk(s[2 * kk][2],     s[2 * kk][3]);
                pA[2] = pk(s[2 * kk + 1][0], s[2 * kk + 1][1]);
                pA[3] = pk(s[2 * kk + 1][2], s[2 * kk + 1][3]);

                const int r0w = (8 * kk + t) * 64;
                const int r1w = (8 * kk + t + 4) * 64;
                const int swz = 8 * t;
                #pragma unroll
                for (int nt = 0; nt < 8; nt++) {
                    int d = 8 * nt + g;
                    uint32_t bf[2] = {Vs[r0w + (d ^ swz)], Vs[r1w + (d ^ swz)]};
                    mma_fp16(o[nt], pA, bf);
                }
            }
        }
    }

    float inv0 = 1.f / l0, inv1 = 1.f / l1;
    size_t r0 = (size_t)(b * TT + q0 + g) * D_MODEL + hcol;
    size_t r1 = (size_t)(b * TT + q0 + g + 8) * D_MODEL + hcol;
    #pragma unroll
    for (int nt = 0; nt < 8; nt++) {
        int cb = nt * 8 + 2 * t;
        *(float2*)&g_y[r0 + cb] = make_float2(o[nt][0] * inv0, o[nt][1] * inv0);
        *(float2*)&g_y[r1 + cb] = make_float2(o[nt][2] * inv1, o[nt][3] * inv1);
    }
}

// ---------------------------------------------------------------------------
extern "C" void kernel_launch(void* const* d_in, const int* in_sizes, int n_in,
                              void* d_out, int out_size) {
    const float* x      = (const float*)d_in[0];
    const float* w_qkv  = (const float*)d_in[1];
    const float* w_proj = (const float*)d_in[2];
    float*       out    = (float*)d_out;

    float *qkv_ptr = nullptr, *y_ptr = nullptr;
    cudaGetSymbolAddress((void**)&qkv_ptr, g_qkv);
    cudaGetSymbolAddress((void**)&y_ptr,   g_y);

    gemm_fp16<<<dim3(3 * D_MODEL / 128, BT / 128), 256>>>(x, w_qkv, qkv_ptr,
                                                          BT, 3 * D_MODEL, D_MODEL);

    attn_fp16<<<dim3(TT / 64, NH, BB), 128>>>();

    gemm_fp16<<<dim3(D_MODEL / 128, BT / 128), 256>>>(y_ptr, w_proj, out,
                                                      BT, D_MODEL, D_MODEL);
}

// round 13
// speedup vs baseline: 1.7429x; 1.2090x over previous
#include <cuda_runtime.h>
#include <cuda_fp16.h>
#include <cstdint>
#include <cstddef>

#define D_MODEL 1024
#define NH      16
#define DH      64
#define BB      4
#define TT      2048
#define BT      (BB * TT)

// fp16 scratch (halves attention/proj staging traffic; quantization moved to
// GEMM epilogue — same rounding as before, applied once)
__device__ __half g_qkv[(size_t)BT * 3 * D_MODEL];   // [B*T, 3072]
__device__ __half g_y  [(size_t)BT * D_MODEL];       // [B*T, 1024]

// ---------------------------------------------------------------------------
__device__ __forceinline__ uint32_t pk(float a, float b) {
    __half2 h = __floats2half2_rn(a, b);
    return *(uint32_t*)&h;
}

__device__ __forceinline__ void mma_fp16(float c[4], const uint32_t a[4],
                                         const uint32_t b[2]) {
    asm volatile(
        "mma.sync.aligned.m16n8k16.row.col.f32.f16.f16.f32 "
        "{%0,%1,%2,%3},{%4,%5,%6,%7},{%8,%9},{%0,%1,%2,%3};"
        : "+f"(c[0]), "+f"(c[1]), "+f"(c[2]), "+f"(c[3])
        : "r"(a[0]), "r"(a[1]), "r"(a[2]), "r"(a[3]), "r"(b[0]), "r"(b[1]));
}

// ---------------------------------------------------------------------------
// FP16 GEMM (round-12 validated structure): C[M,N] = A[M,K] * B[N,K]^T.
// Templated on A element type (float: LDG.128+pack; half: pure uint2 copy)
// and C element type (float: float2 stores; half: packed u32 stores).
// ---------------------------------------------------------------------------
template<typename AT, typename CT>
__global__ __launch_bounds__(256)
void gemm_fp16(const AT* __restrict__ A, const float* __restrict__ Bw,
               CT* __restrict__ C, int M, int N, int K) {
    __shared__ __align__(16) uint32_t As[8 * 2 * 4 * 32];   // 8 KB
    __shared__ __align__(16) uint32_t Bs[16 * 2 * 2 * 32];  // 8 KB

    const int tid    = threadIdx.x;
    const int lane   = tid & 31;
    const int wid    = tid >> 5;
    const int warp_m = wid >> 2;
    const int warp_n = wid & 3;
    const int m0     = blockIdx.y * 128;
    const int n0     = blockIdx.x * 128;
    const int g      = lane >> 2;
    const int t      = lane & 3;

    float acc[4][4][4];
    #pragma unroll
    for (int i = 0; i < 4; i++)
        #pragma unroll
        for (int j = 0; j < 4; j++)
            #pragma unroll
            for (int r = 0; r < 4; r++) acc[i][j][r] = 0.f;

    for (int k0 = 0; k0 < K; k0 += 32) {
        // ---- stage A ----
        #pragma unroll
        for (int it = 0; it < 4; it++) {
            int lin = tid + it * 256;
            int row = lin >> 3;
            int q   = lin & 7;
            uint2 w;
            if constexpr (sizeof(AT) == 2) {
                w = *(const uint2*)&A[(size_t)(m0 + row) * K + k0 + q * 4];
            } else {
                float4 v = *(const float4*)&A[(size_t)(m0 + row) * K + k0 + q * 4];
                w = make_uint2(pk(v.x, v.y), pk(v.z, v.w));
            }
            int plane = ((row >> 4) * 2 + (q >> 2)) * 4 + ((row >> 3) & 1) + 2 * ((q >> 1) & 1);
            int pos0  = ((4 * (row & 7) + 2 * (q & 1))) ^ (4 * q);
            *(uint2*)&As[plane * 32 + pos0] = w;
        }
        // ---- stage B (weights always fp32) ----
        #pragma unroll
        for (int it = 0; it < 4; it++) {
            int lin = tid + it * 256;
            int row = lin >> 3;
            int q   = lin & 7;
            float4 v = *(const float4*)&Bw[(size_t)(n0 + row) * K + k0 + q * 4];
            int plane = ((row >> 3) * 2 + (q >> 2)) * 2 + ((q >> 1) & 1);
            int pos0  = ((4 * (row & 7) + 2 * (q & 1))) ^ (4 * q);
            *(uint2*)&Bs[plane * 32 + pos0] = make_uint2(pk(v.x, v.y), pk(v.z, v.w));
        }
        __syncthreads();

        #pragma unroll
        for (int ks = 0; ks < 2; ks++) {
            const int posLo = (4 * g + t) ^ (4 * (4 * ks + ((t >> 1) & 1)));
            const int posHi = (4 * g + t) ^ (4 * (4 * ks + 2 + ((t >> 1) & 1)));
            uint32_t af[4][4], bf[4][2];
            #pragma unroll
            for (int i = 0; i < 4; i++) {
                int base = (((warp_m * 4 + i) * 2 + ks) * 4) * 32;
                af[i][0] = As[base + posLo];
                af[i][1] = As[base + 32 + posLo];
                af[i][2] = As[base + 64 + posHi];
                af[i][3] = As[base + 96 + posHi];
            }
            #pragma unroll
            for (int j = 0; j < 4; j++) {
                int base = (((warp_n * 4 + j) * 2 + ks) * 2) * 32;
                bf[j][0] = Bs[base + posLo];
                bf[j][1] = Bs[base + 32 + posHi];
            }
            #pragma unroll
            for (int i = 0; i < 4; i++)
                #pragma unroll
                for (int j = 0; j < 4; j++)
                    mma_fp16(acc[i][j], af[i], bf[j]);
        }
        __syncthreads();
    }

    #pragma unroll
    for (int i = 0; i < 4; i++) {
        int rbase = m0 + warp_m * 64 + i * 16 + g;
        #pragma unroll
        for (int j = 0; j < 4; j++) {
            int cbase = n0 + warp_n * 32 + j * 8 + t * 2;
            if constexpr (sizeof(CT) == 2) {
                *(uint32_t*)&C[(size_t)rbase * N + cbase] =
                    pk(acc[i][j][0], acc[i][j][1]);
                *(uint32_t*)&C[(size_t)(rbase + 8) * N + cbase] =
                    pk(acc[i][j][2], acc[i][j][3]);
            } else {
                *(float2*)&C[(size_t)rbase * N + cbase] =
                    make_float2(acc[i][j][0], acc[i][j][1]);
                *(float2*)&C[(size_t)(rbase + 8) * N + cbase] =
                    make_float2(acc[i][j][2], acc[i][j][3]);
            }
        }
    }
}

// ---------------------------------------------------------------------------
// FP16 tensor-core flash attention (round-12 validated structure), fp16 gmem.
// K staging = pure uint2 copy; V transpose via PRMT; Q scaled by hmul2 (exact).
// ---------------------------------------------------------------------------
__global__ __launch_bounds__(128)
void attn_fp16() {
    __shared__ __align__(16) uint32_t Ks[8 * 4 * 2 * 32];   // 8 KB
    __shared__ __align__(16) uint32_t Vs[32 * 64];          // 8 KB

    const int tid  = threadIdx.x;
    const int lane = tid & 31;
    const int w    = tid >> 5;
    const int g    = lane >> 2;
    const int t    = lane & 3;
    const int qt   = (int)(gridDim.x - 1u - blockIdx.x);
    const int h    = blockIdx.y;
    const int b    = blockIdx.z;

    const size_t base = (size_t)b * TT * (3 * D_MODEL);
    const int    hcol = h * DH;
    const int    q0   = qt * 64 + w * 16;

    // Q fragments, scaled by 1/8 via hmul2 (exact power of 2)
    uint32_t qf[4][4];
    {
        const __half2 sc = __half2half2(__float2half(0.125f));
        const __half* qA = g_qkv + base + (size_t)(q0 + g) * (3 * D_MODEL) + hcol;
        const __half* qB = qA + (size_t)8 * (3 * D_MODEL);
        #pragma unroll
        for (int ks = 0; ks < 4; ks++) {
            int d = 16 * ks + 2 * t;
            __half2 v0 = __hmul2(*(const __half2*)(qA + d), sc);
            __half2 v1 = __hmul2(*(const __half2*)(qB + d), sc);
            __half2 v2 = __hmul2(*(const __half2*)(qA + d + 8), sc);
            __half2 v3 = __hmul2(*(const __half2*)(qB + d + 8), sc);
            qf[ks][0] = *(uint32_t*)&v0;
            qf[ks][1] = *(uint32_t*)&v1;
            qf[ks][2] = *(uint32_t*)&v2;
            qf[ks][3] = *(uint32_t*)&v3;
        }
    }

    float m0v = -1e30f, m1v = -1e30f, l0 = 0.f, l1 = 0.f;
    float o[8][4];
    #pragma unroll
    for (int nt = 0; nt < 8; nt++)
        #pragma unroll
        for (int e = 0; e < 4; e++) o[nt][e] = 0.f;

    for (int j = 0; j <= qt; j++) {
        __syncthreads();
        const __half* kp0 = g_qkv + base + (size_t)(j * 64) * (3 * D_MODEL)
                            + D_MODEL + hcol;
        // ---- stage K: pure copy, same index map as round 12 ----
        #pragma unroll
        for (int it = 0; it < 8; it++) {
            int key = (tid & 7) + 8 * it;
            int c   = tid >> 3;                       // 0..15, quad of 4 d
            uint2 wv = *(const uint2*)(kp0 + (size_t)key * (3 * D_MODEL) + c * 4);
            int idx = ((((key >> 3) * 4 + (c >> 2)) * 2 + ((c >> 1) & 1)) << 5)
                      + 4 * (key & 7) + 2 * (c & 1);
            *(uint2*)&Ks[idx] = wv;
        }
        // ---- stage V transposed pairs via PRMT ----
        #pragma unroll
        for (int it = 0; it < 4; it++) {
            int kpair = (tid >> 4) + 8 * it;
            int c     = tid & 15;
            const __half* va = kp0 + (size_t)(2 * kpair) * (3 * D_MODEL) + D_MODEL + c * 4;
            uint2 A2 = *(const uint2*)va;
            uint2 B2 = *(const uint2*)(va + 3 * D_MODEL);
            uint4 wv = make_uint4(__byte_perm(A2.x, B2.x, 0x5410),
                                  __byte_perm(A2.x, B2.x, 0x7632),
                                  __byte_perm(A2.y, B2.y, 0x5410),
                                  __byte_perm(A2.y, B2.y, 0x7632));
            *(uint4*)&Vs[kpair * 64 + ((4 * c) ^ (8 * (kpair & 3)))] = wv;
        }
        __syncthreads();

        const bool diag = (j == qt);
        const int  lim  = diag ? (2 * w + 2) : 8;     // always even

        // ---- S = Q K^T ----
        float s[8][4];
        #pragma unroll
        for (int nt = 0; nt < 8; nt++) {
            if (nt < lim) {
                #pragma unroll
                for (int e = 0; e < 4; e++) s[nt][e] = 0.f;
                #pragma unroll
                for (int ks = 0; ks < 4; ks++) {
                    int kb = ((nt * 4 + ks) * 2) << 5;
                    int pos = 4 * g + t;
                    uint32_t bf[2] = {Ks[kb + pos], Ks[kb + 32 + pos]};
                    mma_fp16(s[nt], qf[ks], bf);
                }
            }
        }

        // ---- causal mask (diagonal tile only) ----
        if (diag) {
            #pragma unroll
            for (int nt = 0; nt < 8; nt++) {
                if (nt < lim) {
                    #pragma unroll
                    for (int e = 0; e < 4; e++) {
                        int keyl = nt * 8 + 2 * t + (e & 1);
                        int rowl = w * 16 + g + ((e >> 1) << 3);
                        if (keyl > rowl) s[nt][e] = -1e30f;
                    }
                }
            }
        }

        // ---- online softmax ----
        float rm0 = -1e30f, rm1 = -1e30f;
        #pragma unroll
        for (int nt = 0; nt < 8; nt++) {
            if (nt < lim) {
                rm0 = fmaxf(rm0, fmaxf(s[nt][0], s[nt][1]));
                rm1 = fmaxf(rm1, fmaxf(s[nt][2], s[nt][3]));
            }
        }
        rm0 = fmaxf(rm0, __shfl_xor_sync(0xffffffffu, rm0, 1));
        rm0 = fmaxf(rm0, __shfl_xor_sync(0xffffffffu, rm0, 2));
        rm1 = fmaxf(rm1, __shfl_xor_sync(0xffffffffu, rm1, 1));
        rm1 = fmaxf(rm1, __shfl_xor_sync(0xffffffffu, rm1, 2));

        float mn0 = fmaxf(m0v, rm0), mn1 = fmaxf(m1v, rm1);
        float a0 = __expf(m0v - mn0), a1 = __expf(m1v - mn1);
        m0v = mn0; m1v = mn1;

        float rs0 = 0.f, rs1 = 0.f;
        #pragma unroll
        for (int nt = 0; nt < 8; nt++) {
            if (nt < lim) {
                s[nt][0] = __expf(s[nt][0] - mn0);
                s[nt][1] = __expf(s[nt][1] - mn0);
                s[nt][2] = __expf(s[nt][2] - mn1);
                s[nt][3] = __expf(s[nt][3] - mn1);
                rs0 += s[nt][0] + s[nt][1];
                rs1 += s[nt][2] + s[nt][3];
            }
        }
        rs0 += __shfl_xor_sync(0xffffffffu, rs0, 1);
        rs0 += __shfl_xor_sync(0xffffffffu, rs0, 2);
        rs1 += __shfl_xor_sync(0xffffffffu, rs1, 1);
        rs1 += __shfl_xor_sync(0xffffffffu, rs1, 2);
        l0 = l0 * a0 + rs0;
        l1 = l1 * a1 + rs1;

        #pragma unroll
        for (int nt = 0; nt < 8; nt++) {
            o[nt][0] *= a0; o[nt][1] *= a0;
            o[nt][2] *= a1; o[nt][3] *= a1;
        }

        // ---- PV: P fragments = packed C-layout pairs (no shuffles) ----
        const int limKK = lim >> 1;
        #pragma unroll
        for (int kk = 0; kk < 4; kk++) {
            if (kk < limKK) {
                uint32_t pA[4];
                pA[0] = pk(s[2 * kk][0],     s[2 * kk][1]);
                pA[1] = pk(s[2 * kk][2],     s[2 * kk][3]);
                pA[2] = pk(s[2 * kk + 1][0], s[2 * kk + 1][1]);
                pA[3] = pk(s[2 * kk + 1][2], s[2 * kk + 1][3]);

                const int r0w = (8 * kk + t) * 64;
                const int r1w = (8 * kk + t + 4) * 64;
                const int swz = 8 * t;
                #pragma unroll
                for (int nt = 0; nt < 8; nt++) {
                    int d = 8 * nt + g;
                    uint32_t bf[2] = {Vs[r0w + (d ^ swz)], Vs[r1w + (d ^ swz)]};
                    mma_fp16(o[nt], pA, bf);
                }
            }
        }
    }

    float inv0 = 1.f / l0, inv1 = 1.f / l1;
    size_t r0 = (size_t)(b * TT + q0 + g) * D_MODEL + hcol;
    size_t r1 = (size_t)(b * TT + q0 + g + 8) * D_MODEL + hcol;
    #pragma unroll
    for (int nt = 0; nt < 8; nt++) {
        int cb = nt * 8 + 2 * t;
        *(uint32_t*)&g_y[r0 + cb] = pk(o[nt][0] * inv0, o[nt][1] * inv0);
        *(uint32_t*)&g_y[r1 + cb] = pk(o[nt][2] * inv1, o[nt][3] * inv1);
    }
}

// ---------------------------------------------------------------------------
extern "C" void kernel_launch(void* const* d_in, const int* in_sizes, int n_in,
                              void* d_out, int out_size) {
    const float* x      = (const float*)d_in[0];
    const float* w_qkv  = (const float*)d_in[1];
    const float* w_proj = (const float*)d_in[2];
    float*       out    = (float*)d_out;

    __half *qkv_ptr = nullptr, *y_ptr = nullptr;
    cudaGetSymbolAddress((void**)&qkv_ptr, g_qkv);
    cudaGetSymbolAddress((void**)&y_ptr,   g_y);

    // 1) qkv(fp16) = x(fp32) @ w_qkv^T
    gemm_fp16<float, __half>
        <<<dim3(3 * D_MODEL / 128, BT / 128), 256>>>(x, w_qkv, qkv_ptr,
                                                     BT, 3 * D_MODEL, D_MODEL);

    // 2) attention (fp16 in/out)
    attn_fp16<<<dim3(TT / 64, NH, BB), 128>>>();

    // 3) out(fp32) = y(fp16) @ w_proj^T
    gemm_fp16<__half, float>
        <<<dim3(D_MODEL / 128, BT / 128), 256>>>(y_ptr, w_proj, out,
                                                 BT, D_MODEL, D_MODEL);
}

// round 15
// speedup vs baseline: 1.7652x; 1.0128x over previous
#include <cuda_runtime.h>
#include <cuda_fp16.h>
#include <cstdint>
#include <cstddef>

#define D_MODEL 1024
#define NH      16
#define DH      64
#define BB      4
#define TT      2048
#define BT      (BB * TT)

__device__ __half g_qkv[(size_t)BT * 3 * D_MODEL];   // [B*T, 3072]
__device__ __half g_y  [(size_t)BT * D_MODEL];       // [B*T, 1024]
__device__ __half g_x  [(size_t)BT * D_MODEL];       // fp16 copy of x
__device__ __half g_wq [(size_t)3 * D_MODEL * D_MODEL];
__device__ __half g_wp [(size_t)D_MODEL * D_MODEL];

// ---------------------------------------------------------------------------
__device__ __forceinline__ uint32_t pk(float a, float b) {
    __half2 h = __floats2half2_rn(a, b);
    return *(uint32_t*)&h;
}

__device__ __forceinline__ void mma_fp16(float c[4], const uint32_t a[4],
                                         const uint32_t b[2]) {
    asm volatile(
        "mma.sync.aligned.m16n8k16.row.col.f32.f16.f16.f32 "
        "{%0,%1,%2,%3},{%4,%5,%6,%7},{%8,%9},{%0,%1,%2,%3};"
        : "+f"(c[0]), "+f"(c[1]), "+f"(c[2]), "+f"(c[3])
        : "r"(a[0]), "r"(a[1]), "r"(a[2]), "r"(a[3]), "r"(b[0]), "r"(b[1]));
}

__device__ __forceinline__ uint32_t smem_u32(const void* p) {
    uint32_t a;
    asm("{ .reg .u64 t; cvta.to.shared.u64 t, %1; cvt.u32.u64 %0, t; }"
        : "=r"(a) : "l"(p));
    return a;
}

__device__ __forceinline__ void cpa8(uint32_t dst, const void* src) {
    asm volatile("cp.async.ca.shared.global [%0], [%1], 8;"
                 :: "r"(dst), "l"(src) : "memory");
}

// ---------------------------------------------------------------------------
// fp32 -> fp16 conversion (4 elems/thread), same __floats2half2_rn rounding
// as the previous in-staging cvt (bit-identical downstream values).
// ---------------------------------------------------------------------------
__global__ __launch_bounds__(256)
void f2h(const float* __restrict__ src, __half* __restrict__ dst) {
    int i = (blockIdx.x * 256 + threadIdx.x) * 4;
    float4 v = *(const float4*)&src[i];
    *(uint2*)&dst[i] = make_uint2(pk(v.x, v.y), pk(v.z, v.w));
}

// ---------------------------------------------------------------------------
// FP16 GEMM v2 (fixed): all-fp16 operands, cp.async.ca double-buffered.
// 128x128 block, 8 warps (64x32), K-chunk 32, fragment-order swizzled smem.
// Per-buffer strides: A = 2048 words, B = 2048 words.
// ---------------------------------------------------------------------------
template<typename CT>
__global__ __launch_bounds__(256)
void gemm_fp16(const __half* __restrict__ A, const __half* __restrict__ Bw,
               CT* __restrict__ C, int M, int N, int K) {
    __shared__ __align__(16) uint32_t As[2][8 * 2 * 4 * 32];   // 2 x 2048 words
    __shared__ __align__(16) uint32_t Bs[2][16 * 2 * 2 * 32];  // 2 x 2048 words

    const int tid    = threadIdx.x;
    const int lane   = tid & 31;
    const int wid    = tid >> 5;
    const int warp_m = wid >> 2;
    const int warp_n = wid & 3;
    const int m0     = blockIdx.y * 128;
    const int n0     = blockIdx.x * 128;
    const int g      = lane >> 2;
    const int t      = lane & 3;

    const uint32_t aBase = smem_u32(As);
    const uint32_t bBase = smem_u32(Bs);

    float acc[4][4][4];
    #pragma unroll
    for (int i = 0; i < 4; i++)
        #pragma unroll
        for (int j = 0; j < 4; j++)
            #pragma unroll
            for (int r = 0; r < 4; r++) acc[i][j][r] = 0.f;

    const int NCH = K / 32;

    // ---- stage chunk 0 into buffer 0 ----
    #pragma unroll
    for (int it = 0; it < 4; it++) {
        int lin = tid + it * 256;
        int row = lin >> 3;
        int q   = lin & 7;
        int pos0 = ((4 * (row & 7) + 2 * (q & 1))) ^ (4 * q);
        int planeA = ((row >> 4) * 2 + (q >> 2)) * 4 + ((row >> 3) & 1) + 2 * ((q >> 1) & 1);
        cpa8(aBase + (planeA * 32 + pos0) * 4, &A[(size_t)(m0 + row) * K + q * 4]);
        int planeB = ((row >> 3) * 2 + (q >> 2)) * 2 + ((q >> 1) & 1);
        cpa8(bBase + (planeB * 32 + pos0) * 4, &Bw[(size_t)(n0 + row) * K + q * 4]);
    }
    asm volatile("cp.async.commit_group;" ::: "memory");

    for (int c = 0; c < NCH; c++) {
        const int cur = c & 1;
        if (c + 1 < NCH) {
            const int nb = (c + 1) & 1;
            const int k0 = (c + 1) * 32;
            #pragma unroll
            for (int it = 0; it < 4; it++) {
                int lin = tid + it * 256;
                int row = lin >> 3;
                int q   = lin & 7;
                int pos0 = ((4 * (row & 7) + 2 * (q & 1))) ^ (4 * q);
                int planeA = ((row >> 4) * 2 + (q >> 2)) * 4 + ((row >> 3) & 1) + 2 * ((q >> 1) & 1);
                cpa8(aBase + (nb * 2048 + planeA * 32 + pos0) * 4,
                     &A[(size_t)(m0 + row) * K + k0 + q * 4]);
                int planeB = ((row >> 3) * 2 + (q >> 2)) * 2 + ((q >> 1) & 1);
                cpa8(bBase + (nb * 2048 + planeB * 32 + pos0) * 4,
                     &Bw[(size_t)(n0 + row) * K + k0 + q * 4]);
            }
            asm volatile("cp.async.commit_group;" ::: "memory");
            asm volatile("cp.async.wait_group 1;" ::: "memory");
        } else {
            asm volatile("cp.async.wait_group 0;" ::: "memory");
        }
        __syncthreads();

        const uint32_t* Ab = As[cur];
        const uint32_t* Bb = Bs[cur];
        #pragma unroll
        for (int ks = 0; ks < 2; ks++) {
            const int posLo = (4 * g + t) ^ (4 * (4 * ks + ((t >> 1) & 1)));
            const int posHi = (4 * g + t) ^ (4 * (4 * ks + 2 + ((t >> 1) & 1)));
            uint32_t af[4][4], bf[4][2];
            #pragma unroll
            for (int i = 0; i < 4; i++) {
                int base = (((warp_m * 4 + i) * 2 + ks) * 4) * 32;
                af[i][0] = Ab[base + posLo];
                af[i][1] = Ab[base + 32 + posLo];
                af[i][2] = Ab[base + 64 + posHi];
                af[i][3] = Ab[base + 96 + posHi];
            }
            #pragma unroll
            for (int j = 0; j < 4; j++) {
                int base = (((warp_n * 4 + j) * 2 + ks) * 2) * 32;
                bf[j][0] = Bb[base + posLo];
                bf[j][1] = Bb[base + 32 + posHi];
            }
            #pragma unroll
            for (int i = 0; i < 4; i++)
                #pragma unroll
                for (int j = 0; j < 4; j++)
                    mma_fp16(acc[i][j], af[i], bf[j]);
        }
        __syncthreads();   // reads of buf[cur] done before restage (c+2)
    }

    #pragma unroll
    for (int i = 0; i < 4; i++) {
        int rbase = m0 + warp_m * 64 + i * 16 + g;
        #pragma unroll
        for (int j = 0; j < 4; j++) {
            int cbase = n0 + warp_n * 32 + j * 8 + t * 2;
            if constexpr (sizeof(CT) == 2) {
                *(uint32_t*)&C[(size_t)rbase * N + cbase] =
                    pk(acc[i][j][0], acc[i][j][1]);
                *(uint32_t*)&C[(size_t)(rbase + 8) * N + cbase] =
                    pk(acc[i][j][2], acc[i][j][3]);
            } else {
                *(float2*)&C[(size_t)rbase * N + cbase] =
                    make_float2(acc[i][j][0], acc[i][j][1]);
                *(float2*)&C[(size_t)(rbase + 8) * N + cbase] =
                    make_float2(acc[i][j][2], acc[i][j][3]);
            }
        }
    }
}

// ---------------------------------------------------------------------------
// FP16 tensor-core flash attention (round-13 validated, unchanged).
// ---------------------------------------------------------------------------
__global__ __launch_bounds__(128)
void attn_fp16() {
    __shared__ __align__(16) uint32_t Ks[8 * 4 * 2 * 32];   // 8 KB
    __shared__ __align__(16) uint32_t Vs[32 * 64];          // 8 KB

    const int tid  = threadIdx.x;
    const int lane = tid & 31;
    const int w    = tid >> 5;
    const int g    = lane >> 2;
    const int t    = lane & 3;
    const int qt   = (int)(gridDim.x - 1u - blockIdx.x);
    const int h    = blockIdx.y;
    const int b    = blockIdx.z;

    const size_t base = (size_t)b * TT * (3 * D_MODEL);
    const int    hcol = h * DH;
    const int    q0   = qt * 64 + w * 16;

    uint32_t qf[4][4];
    {
        const __half2 sc = __half2half2(__float2half(0.125f));
        const __half* qA = g_qkv + base + (size_t)(q0 + g) * (3 * D_MODEL) + hcol;
        const __half* qB = qA + (size_t)8 * (3 * D_MODEL);
        #pragma unroll
        for (int ks = 0; ks < 4; ks++) {
            int d = 16 * ks + 2 * t;
            __half2 v0 = __hmul2(*(const __half2*)(qA + d), sc);
            __half2 v1 = __hmul2(*(const __half2*)(qB + d), sc);
            __half2 v2 = __hmul2(*(const __half2*)(qA + d + 8), sc);
            __half2 v3 = __hmul2(*(const __half2*)(qB + d + 8), sc);
            qf[ks][0] = *(uint32_t*)&v0;
            qf[ks][1] = *(uint32_t*)&v1;
            qf[ks][2] = *(uint32_t*)&v2;
            qf[ks][3] = *(uint32_t*)&v3;
        }
    }

    float m0v = -1e30f, m1v = -1e30f, l0 = 0.f, l1 = 0.f;
    float o[8][4];
    #pragma unroll
    for (int nt = 0; nt < 8; nt++)
        #pragma unroll
        for (int e = 0; e < 4; e++) o[nt][e] = 0.f;

    for (int j = 0; j <= qt; j++) {
        __syncthreads();
        const __half* kp0 = g_qkv + base + (size_t)(j * 64) * (3 * D_MODEL)
                            + D_MODEL + hcol;
        #pragma unroll
        for (int it = 0; it < 8; it++) {
            int key = (tid & 7) + 8 * it;
            int c   = tid >> 3;
            uint2 wv = *(const uint2*)(kp0 + (size_t)key * (3 * D_MODEL) + c * 4);
            int idx = ((((key >> 3) * 4 + (c >> 2)) * 2 + ((c >> 1) & 1)) << 5)
                      + 4 * (key & 7) + 2 * (c & 1);
            *(uint2*)&Ks[idx] = wv;
        }
        #pragma unroll
        for (int it = 0; it < 4; it++) {
            int kpair = (tid >> 4) + 8 * it;
            int c     = tid & 15;
            const __half* va = kp0 + (size_t)(2 * kpair) * (3 * D_MODEL) + D_MODEL + c * 4;
            uint2 A2 = *(const uint2*)va;
            uint2 B2 = *(const uint2*)(va + 3 * D_MODEL);
            uint4 wv = make_uint4(__byte_perm(A2.x, B2.x, 0x5410),
                                  __byte_perm(A2.x, B2.x, 0x7632),
                                  __byte_perm(A2.y, B2.y, 0x5410),
                                  __byte_perm(A2.y, B2.y, 0x7632));
            *(uint4*)&Vs[kpair * 64 + ((4 * c) ^ (8 * (kpair & 3)))] = wv;
        }
        __syncthreads();

        const bool diag = (j == qt);
        const int  lim  = diag ? (2 * w + 2) : 8;

        float s[8][4];
        #pragma unroll
        for (int nt = 0; nt < 8; nt++) {
            if (nt < lim) {
                #pragma unroll
                for (int e = 0; e < 4; e++) s[nt][e] = 0.f;
                #pragma unroll
                for (int ks = 0; ks < 4; ks++) {
                    int kb = ((nt * 4 + ks) * 2) << 5;
                    int pos = 4 * g + t;
                    uint32_t bf[2] = {Ks[kb + pos], Ks[kb + 32 + pos]};
                    mma_fp16(s[nt], qf[ks], bf);
                }
            }
        }

        if (diag) {
            #pragma unroll
            for (int nt = 0; nt < 8; nt++) {
                if (nt < lim) {
                    #pragma unroll
                    for (int e = 0; e < 4; e++) {
                        int keyl = nt * 8 + 2 * t + (e & 1);
                        int rowl = w * 16 + g + ((e >> 1) << 3);
                        if (keyl > rowl) s[nt][e] = -1e30f;
                    }
                }
            }
        }

        float rm0 = -1e30f, rm1 = -1e30f;
        #pragma unroll
        for (int nt = 0; nt < 8; nt++) {
            if (nt < lim) {
                rm0 = fmaxf(rm0, fmaxf(s[nt][0], s[nt][1]));
                rm1 = fmaxf(rm1, fmaxf(s[nt][2], s[nt][3]));
            }
        }
        rm0 = fmaxf(rm0, __shfl_xor_sync(0xffffffffu, rm0, 1));
        rm0 = fmaxf(rm0, __shfl_xor_sync(0xffffffffu, rm0, 2));
        rm1 = fmaxf(rm1, __shfl_xor_sync(0xffffffffu, rm1, 1));
        rm1 = fmaxf(rm1, __shfl_xor_sync(0xffffffffu, rm1, 2));

        float mn0 = fmaxf(m0v, rm0), mn1 = fmaxf(m1v, rm1);
        float a0 = __expf(m0v - mn0), a1 = __expf(m1v - mn1);
        m0v = mn0; m1v = mn1;

        float rs0 = 0.f, rs1 = 0.f;
        #pragma unroll
        for (int nt = 0; nt < 8; nt++) {
            if (nt < lim) {
                s[nt][0] = __expf(s[nt][0] - mn0);
                s[nt][1] = __expf(s[nt][1] - mn0);
                s[nt][2] = __expf(s[nt][2] - mn1);
                s[nt][3] = __expf(s[nt][3] - mn1);
                rs0 += s[nt][0] + s[nt][1];
                rs1 += s[nt][2] + s[nt][3];
            }
        }
        rs0 += __shfl_xor_sync(0xffffffffu, rs0, 1);
        rs0 += __shfl_xor_sync(0xffffffffu, rs0, 2);
        rs1 += __shfl_xor_sync(0xffffffffu, rs1, 1);
        rs1 += __shfl_xor_sync(0xffffffffu, rs1, 2);
        l0 = l0 * a0 + rs0;
        l1 = l1 * a1 + rs1;

        #pragma unroll
        for (int nt = 0; nt < 8; nt++) {
            o[nt][0] *= a0; o[nt][1] *= a0;
            o[nt][2] *= a1; o[nt][3] *= a1;
        }

        const int limKK = lim >> 1;
        #pragma unroll
        for (int kk = 0; kk < 4; kk++) {
            if (kk < limKK) {
                uint32_t pA[4];
                pA[0] = pk(s[2 * kk][0],     s[2 * kk][1]);
                pA[1] = pk(s[2 * kk][2],     s[2 * kk][3]);
                pA[2] = pk(s[2 * kk + 1][0], s[2 * kk + 1][1]);
                pA[3] = pk(s[2 * kk + 1][2], s[2 * kk + 1][3]);

                const int r0w = (8 * kk + t) * 64;
                const int r1w = (8 * kk + t + 4) * 64;
                const int swz = 8 * t;
                #pragma unroll
                for (int nt = 0; nt < 8; nt++) {
                    int d = 8 * nt + g;
                    uint32_t bf[2] = {Vs[r0w + (d ^ swz)], Vs[r1w + (d ^ swz)]};
                    mma_fp16(o[nt], pA, bf);
                }
            }
        }
    }

    float inv0 = 1.f / l0, inv1 = 1.f / l1;
    size_t r0 = (size_t)(b * TT + q0 + g) * D_MODEL + hcol;
    size_t r1 = (size_t)(b * TT + q0 + g + 8) * D_MODEL + hcol;
    #pragma unroll
    for (int nt = 0; nt < 8; nt++) {
        int cb = nt * 8 + 2 * t;
        *(uint32_t*)&g_y[r0 + cb] = pk(o[nt][0] * inv0, o[nt][1] * inv0);
        *(uint32_t*)&g_y[r1 + cb] = pk(o[nt][2] * inv1, o[nt][3] * inv1);
    }
}

// ---------------------------------------------------------------------------
extern "C" void kernel_launch(void* const* d_in, const int* in_sizes, int n_in,
                              void* d_out, int out_size) {
    const float* x      = (const float*)d_in[0];
    const float* w_qkv  = (const float*)d_in[1];
    const float* w_proj = (const float*)d_in[2];
    float*       out    = (float*)d_out;

    __half *qkv_p, *y_p, *x_p, *wq_p, *wp_p;
    cudaGetSymbolAddress((void**)&qkv_p, g_qkv);
    cudaGetSymbolAddress((void**)&y_p,   g_y);
    cudaGetSymbolAddress((void**)&x_p,   g_x);
    cudaGetSymbolAddress((void**)&wq_p,  g_wq);
    cudaGetSymbolAddress((void**)&wp_p,  g_wp);

    // 0) fp32 -> fp16 conversions (same rounding as previous in-staging cvt)
    f2h<<<(BT * D_MODEL) / 1024, 256>>>(x, x_p);
    f2h<<<(3 * D_MODEL * D_MODEL) / 1024, 256>>>(w_qkv, wq_p);
    f2h<<<(D_MODEL * D_MODEL) / 1024, 256>>>(w_proj, wp_p);

    // 1) qkv(fp16) = x @ w_qkv^T
    gemm_fp16<__half>
        <<<dim3(3 * D_MODEL / 128, BT / 128), 256>>>(x_p, wq_p, qkv_p,
                                                     BT, 3 * D_MODEL, D_MODEL);

    // 2) attention (fp16 in/out)
    attn_fp16<<<dim3(TT / 64, NH, BB), 128>>>();

    // 3) out(fp32) = y @ w_proj^T
    gemm_fp16<float>
        <<<dim3(D_MODEL / 128, BT / 128), 256>>>(y_p, wp_p, out,
                                                 BT, D_MODEL, D_MODEL);
}

// round 16
// speedup vs baseline: 1.9030x; 1.0781x over previous
#include <cuda_runtime.h>
#include <cuda_fp16.h>
#include <cstdint>
#include <cstddef>

#define D_MODEL 1024
#define NH      16
#define DH      64
#define BB      4
#define TT      2048
#define BT      (BB * TT)

__device__ __half g_qkv[(size_t)BT * 3 * D_MODEL];   // [B*T, 3072]
__device__ __half g_y  [(size_t)BT * D_MODEL];       // [B*T, 1024]
__device__ __half g_x  [(size_t)BT * D_MODEL];       // fp16 copy of x
__device__ __half g_wq [(size_t)3 * D_MODEL * D_MODEL];
__device__ __half g_wp [(size_t)D_MODEL * D_MODEL];

// ---------------------------------------------------------------------------
__device__ __forceinline__ uint32_t pk(float a, float b) {
    __half2 h = __floats2half2_rn(a, b);
    return *(uint32_t*)&h;
}

__device__ __forceinline__ void mma_fp16(float c[4], const uint32_t a[4],
                                         const uint32_t b[2]) {
    asm volatile(
        "mma.sync.aligned.m16n8k16.row.col.f32.f16.f16.f32 "
        "{%0,%1,%2,%3},{%4,%5,%6,%7},{%8,%9},{%0,%1,%2,%3};"
        : "+f"(c[0]), "+f"(c[1]), "+f"(c[2]), "+f"(c[3])
        : "r"(a[0]), "r"(a[1]), "r"(a[2]), "r"(a[3]), "r"(b[0]), "r"(b[1]));
}

__device__ __forceinline__ uint32_t smem_u32(const void* p) {
    uint32_t a;
    asm("{ .reg .u64 t; cvta.to.shared.u64 t, %1; cvt.u32.u64 %0, t; }"
        : "=r"(a) : "l"(p));
    return a;
}

__device__ __forceinline__ void cpa8(uint32_t dst, const void* src) {
    asm volatile("cp.async.ca.shared.global [%0], [%1], 8;"
                 :: "r"(dst), "l"(src) : "memory");
}

// ---------------------------------------------------------------------------
// fp32 -> fp16 conversion (4 elems/thread).
// ---------------------------------------------------------------------------
__global__ __launch_bounds__(256)
void f2h(const float* __restrict__ src, __half* __restrict__ dst) {
    int i = (blockIdx.x * 256 + threadIdx.x) * 4;
    float4 v = *(const float4*)&src[i];
    *(uint2*)&dst[i] = make_uint2(pk(v.x, v.y), pk(v.z, v.w));
}

// ---------------------------------------------------------------------------
// FP16 GEMM v3: all-fp16 operands, cp.async.ca double-buffered, 2 CTAs/SM.
// 128x128 block, 8 warps (64x32), K-chunk 32, fragment-order swizzled smem.
// Staging coordinates hoisted out of the chunk loop (loop-invariant).
// ---------------------------------------------------------------------------
template<typename CT>
__global__ __launch_bounds__(256, 2)
void gemm_fp16(const __half* __restrict__ A, const __half* __restrict__ Bw,
               CT* __restrict__ C, int M, int N, int K) {
    __shared__ __align__(16) uint32_t As[2][8 * 2 * 4 * 32];   // 2 x 2048 words
    __shared__ __align__(16) uint32_t Bs[2][16 * 2 * 2 * 32];  // 2 x 2048 words

    const int tid    = threadIdx.x;
    const int lane   = tid & 31;
    const int wid    = tid >> 5;
    const int warp_m = wid >> 2;
    const int warp_n = wid & 3;
    const int m0     = blockIdx.y * 128;
    const int n0     = blockIdx.x * 128;
    const int g      = lane >> 2;
    const int t      = lane & 3;

    // ---- hoisted per-thread staging coords (invariant across chunks) ----
    uint32_t dstA[4], dstB[4];          // smem byte offsets within buffer 0
    const __half* srcA[4];              // gmem pointers (advance by 32/chunk)
    const __half* srcB[4];
    {
        const uint32_t aBase = smem_u32(As);
        const uint32_t bBase = smem_u32(Bs);
        #pragma unroll
        for (int it = 0; it < 4; it++) {
            int lin = tid + it * 256;
            int row = lin >> 3;
            int q   = lin & 7;
            int pos0 = ((4 * (row & 7) + 2 * (q & 1))) ^ (4 * q);
            int planeA = ((row >> 4) * 2 + (q >> 2)) * 4 + ((row >> 3) & 1) + 2 * ((q >> 1) & 1);
            int planeB = ((row >> 3) * 2 + (q >> 2)) * 2 + ((q >> 1) & 1);
            dstA[it] = aBase + (planeA * 32 + pos0) * 4;
            dstB[it] = bBase + (planeB * 32 + pos0) * 4;
            srcA[it] = &A[(size_t)(m0 + row) * K + q * 4];
            srcB[it] = &Bw[(size_t)(n0 + row) * K + q * 4];
        }
    }

    float acc[4][4][4];
    #pragma unroll
    for (int i = 0; i < 4; i++)
        #pragma unroll
        for (int j = 0; j < 4; j++)
            #pragma unroll
            for (int r = 0; r < 4; r++) acc[i][j][r] = 0.f;

    const int NCH = K / 32;

    // ---- stage chunk 0 into buffer 0 ----
    #pragma unroll
    for (int it = 0; it < 4; it++) {
        cpa8(dstA[it], srcA[it]);
        cpa8(dstB[it], srcB[it]);
    }
    asm volatile("cp.async.commit_group;" ::: "memory");

    for (int c = 0; c < NCH; c++) {
        const int cur = c & 1;
        if (c + 1 < NCH) {
            const uint32_t nb = ((c + 1) & 1) * 8192;   // bytes (2048 words)
            const int koff = (c + 1) * 32;
            #pragma unroll
            for (int it = 0; it < 4; it++) {
                cpa8(dstA[it] + nb, srcA[it] + koff);
                cpa8(dstB[it] + nb, srcB[it] + koff);
            }
            asm volatile("cp.async.commit_group;" ::: "memory");
            asm volatile("cp.async.wait_group 1;" ::: "memory");
        } else {
            asm volatile("cp.async.wait_group 0;" ::: "memory");
        }
        __syncthreads();

        const uint32_t* Ab = As[cur];
        const uint32_t* Bb = Bs[cur];
        #pragma unroll
        for (int ks = 0; ks < 2; ks++) {
            const int posLo = (4 * g + t) ^ (4 * (4 * ks + ((t >> 1) & 1)));
            const int posHi = (4 * g + t) ^ (4 * (4 * ks + 2 + ((t >> 1) & 1)));
            uint32_t af[4][4], bf[4][2];
            #pragma unroll
            for (int i = 0; i < 4; i++) {
                int base = (((warp_m * 4 + i) * 2 + ks) * 4) * 32;
                af[i][0] = Ab[base + posLo];
                af[i][1] = Ab[base + 32 + posLo];
                af[i][2] = Ab[base + 64 + posHi];
                af[i][3] = Ab[base + 96 + posHi];
            }
            #pragma unroll
            for (int j = 0; j < 4; j++) {
                int base = (((warp_n * 4 + j) * 2 + ks) * 2) * 32;
                bf[j][0] = Bb[base + posLo];
                bf[j][1] = Bb[base + 32 + posHi];
            }
            #pragma unroll
            for (int i = 0; i < 4; i++)
                #pragma unroll
                for (int j = 0; j < 4; j++)
                    mma_fp16(acc[i][j], af[i], bf[j]);
        }
        __syncthreads();   // reads of buf[cur] done before restage (c+2)
    }

    #pragma unroll
    for (int i = 0; i < 4; i++) {
        int rbase = m0 + warp_m * 64 + i * 16 + g;
        #pragma unroll
        for (int j = 0; j < 4; j++) {
            int cbase = n0 + warp_n * 32 + j * 8 + t * 2;
            if constexpr (sizeof(CT) == 2) {
                *(uint32_t*)&C[(size_t)rbase * N + cbase] =
                    pk(acc[i][j][0], acc[i][j][1]);
                *(uint32_t*)&C[(size_t)(rbase + 8) * N + cbase] =
                    pk(acc[i][j][2], acc[i][j][3]);
            } else {
                *(float2*)&C[(size_t)rbase * N + cbase] =
                    make_float2(acc[i][j][0], acc[i][j][1]);
                *(float2*)&C[(size_t)(rbase + 8) * N + cbase] =
                    make_float2(acc[i][j][2], acc[i][j][3]);
            }
        }
    }
}

// ---------------------------------------------------------------------------
// FP16 tensor-core flash attention (round-13 validated, unchanged).
// ---------------------------------------------------------------------------
__global__ __launch_bounds__(128)
void attn_fp16() {
    __shared__ __align__(16) uint32_t Ks[8 * 4 * 2 * 32];   // 8 KB
    __shared__ __align__(16) uint32_t Vs[32 * 64];          // 8 KB

    const int tid  = threadIdx.x;
    const int lane = tid & 31;
    const int w    = tid >> 5;
    const int g    = lane >> 2;
    const int t    = lane & 3;
    const int qt   = (int)(gridDim.x - 1u - blockIdx.x);
    const int h    = blockIdx.y;
    const int b    = blockIdx.z;

    const size_t base = (size_t)b * TT * (3 * D_MODEL);
    const int    hcol = h * DH;
    const int    q0   = qt * 64 + w * 16;

    uint32_t qf[4][4];
    {
        const __half2 sc = __half2half2(__float2half(0.125f));
        const __half* qA = g_qkv + base + (size_t)(q0 + g) * (3 * D_MODEL) + hcol;
        const __half* qB = qA + (size_t)8 * (3 * D_MODEL);
        #pragma unroll
        for (int ks = 0; ks < 4; ks++) {
            int d = 16 * ks + 2 * t;
            __half2 v0 = __hmul2(*(const __half2*)(qA + d), sc);
            __half2 v1 = __hmul2(*(const __half2*)(qB + d), sc);
            __half2 v2 = __hmul2(*(const __half2*)(qA + d + 8), sc);
            __half2 v3 = __hmul2(*(const __half2*)(qB + d + 8), sc);
            qf[ks][0] = *(uint32_t*)&v0;
            qf[ks][1] = *(uint32_t*)&v1;
            qf[ks][2] = *(uint32_t*)&v2;
            qf[ks][3] = *(uint32_t*)&v3;
        }
    }

    float m0v = -1e30f, m1v = -1e30f, l0 = 0.f, l1 = 0.f;
    float o[8][4];
    #pragma unroll
    for (int nt = 0; nt < 8; nt++)
        #pragma unroll
        for (int e = 0; e < 4; e++) o[nt][e] = 0.f;

    for (int j = 0; j <= qt; j++) {
        __syncthreads();
        const __half* kp0 = g_qkv + base + (size_t)(j * 64) * (3 * D_MODEL)
                            + D_MODEL + hcol;
        #pragma unroll
        for (int it = 0; it < 8; it++) {
            int key = (tid & 7) + 8 * it;
            int c   = tid >> 3;
            uint2 wv = *(const uint2*)(kp0 + (size_t)key * (3 * D_MODEL) + c * 4);
            int idx = ((((key >> 3) * 4 + (c >> 2)) * 2 + ((c >> 1) & 1)) << 5)
                      + 4 * (key & 7) + 2 * (c & 1);
            *(uint2*)&Ks[idx] = wv;
        }
        #pragma unroll
        for (int it = 0; it < 4; it++) {
            int kpair = (tid >> 4) + 8 * it;
            int c     = tid & 15;
            const __half* va = kp0 + (size_t)(2 * kpair) * (3 * D_MODEL) + D_MODEL + c * 4;
            uint2 A2 = *(const uint2*)va;
            uint2 B2 = *(const uint2*)(va + 3 * D_MODEL);
            uint4 wv = make_uint4(__byte_perm(A2.x, B2.x, 0x5410),
                                  __byte_perm(A2.x, B2.x, 0x7632),
                                  __byte_perm(A2.y, B2.y, 0x5410),
                                  __byte_perm(A2.y, B2.y, 0x7632));
            *(uint4*)&Vs[kpair * 64 + ((4 * c) ^ (8 * (kpair & 3)))] = wv;
        }
        __syncthreads();

        const bool diag = (j == qt);
        const int  lim  = diag ? (2 * w + 2) : 8;

        float s[8][4];
        #pragma unroll
        for (int nt = 0; nt < 8; nt++) {
            if (nt < lim) {
                #pragma unroll
                for (int e = 0; e < 4; e++) s[nt][e] = 0.f;
                #pragma unroll
                for (int ks = 0; ks < 4; ks++) {
                    int kb = ((nt * 4 + ks) * 2) << 5;
                    int pos = 4 * g + t;
                    uint32_t bf[2] = {Ks[kb + pos], Ks[kb + 32 + pos]};
                    mma_fp16(s[nt], qf[ks], bf);
                }
            }
        }

        if (diag) {
            #pragma unroll
            for (int nt = 0; nt < 8; nt++) {
                if (nt < lim) {
                    #pragma unroll
                    for (int e = 0; e < 4; e++) {
                        int keyl = nt * 8 + 2 * t + (e & 1);
                        int rowl = w * 16 + g + ((e >> 1) << 3);
                        if (keyl > rowl) s[nt][e] = -1e30f;
                    }
                }
            }
        }

        float rm0 = -1e30f, rm1 = -1e30f;
        #pragma unroll
        for (int nt = 0; nt < 8; nt++) {
            if (nt < lim) {
                rm0 = fmaxf(rm0, fmaxf(s[nt][0], s[nt][1]));
                rm1 = fmaxf(rm1, fmaxf(s[nt][2], s[nt][3]));
            }
        }
        rm0 = fmaxf(rm0, __shfl_xor_sync(0xffffffffu, rm0, 1));
        rm0 = fmaxf(rm0, __shfl_xor_sync(0xffffffffu, rm0, 2));
        rm1 = fmaxf(rm1, __shfl_xor_sync(0xffffffffu, rm1, 1));
        rm1 = fmaxf(rm1, __shfl_xor_sync(0xffffffffu, rm1, 2));

        float mn0 = fmaxf(m0v, rm0), mn1 = fmaxf(m1v, rm1);
        float a0 = __expf(m0v - mn0), a1 = __expf(m1v - mn1);
        m0v = mn0; m1v = mn1;

        float rs0 = 0.f, rs1 = 0.f;
        #pragma unroll
        for (int nt = 0; nt < 8; nt++) {
            if (nt < lim) {
                s[nt][0] = __expf(s[nt][0] - mn0);
                s[nt][1] = __expf(s[nt][1] - mn0);
                s[nt][2] = __expf(s[nt][2] - mn1);
                s[nt][3] = __expf(s[nt][3] - mn1);
                rs0 += s[nt][0] + s[nt][1];
                rs1 += s[nt][2] + s[nt][3];
            }
        }
        rs0 += __shfl_xor_sync(0xffffffffu, rs0, 1);
        rs0 += __shfl_xor_sync(0xffffffffu, rs0, 2);
        rs1 += __shfl_xor_sync(0xffffffffu, rs1, 1);
        rs1 += __shfl_xor_sync(0xffffffffu, rs1, 2);
        l0 = l0 * a0 + rs0;
        l1 = l1 * a1 + rs1;

        #pragma unroll
        for (int nt = 0; nt < 8; nt++) {
            o[nt][0] *= a0; o[nt][1] *= a0;
            o[nt][2] *= a1; o[nt][3] *= a1;
        }

        const int limKK = lim >> 1;
        #pragma unroll
        for (int kk = 0; kk < 4; kk++) {
            if (kk < limKK) {
                uint32_t pA[4];
                pA[0] = pk(s[2 * kk][0],     s[2 * kk][1]);
                pA[1] = pk(s[2 * kk][2],     s[2 * kk][3]);
                pA[2] = pk(s[2 * kk + 1][0], s[2 * kk + 1][1]);
                pA[3] = pk(s[2 * kk + 1][2], s[2 * kk + 1][3]);

                const int r0w = (8 * kk + t) * 64;
                const int r1w = (8 * kk + t + 4) * 64;
                const int swz = 8 * t;
                #pragma unroll
                for (int nt = 0; nt < 8; nt++) {
                    int d = 8 * nt + g;
                    uint32_t bf[2] = {Vs[r0w + (d ^ swz)], Vs[r1w + (d ^ swz)]};
                    mma_fp16(o[nt], pA, bf);
                }
            }
        }
    }

    float inv0 = 1.f / l0, inv1 = 1.f / l1;
    size_t r0 = (size_t)(b * TT + q0 + g) * D_MODEL + hcol;
    size_t r1 = (size_t)(b * TT + q0 + g + 8) * D_MODEL + hcol;
    #pragma unroll
    for (int nt = 0; nt < 8; nt++) {
        int cb = nt * 8 + 2 * t;
        *(uint32_t*)&g_y[r0 + cb] = pk(o[nt][0] * inv0, o[nt][1] * inv0);
        *(uint32_t*)&g_y[r1 + cb] = pk(o[nt][2] * inv1, o[nt][3] * inv1);
    }
}

// ---------------------------------------------------------------------------
extern "C" void kernel_launch(void* const* d_in, const int* in_sizes, int n_in,
                              void* d_out, int out_size) {
    const float* x      = (const float*)d_in[0];
    const float* w_qkv  = (const float*)d_in[1];
    const float* w_proj = (const float*)d_in[2];
    float*       out    = (float*)d_out;

    __half *qkv_p, *y_p, *x_p, *wq_p, *wp_p;
    cudaGetSymbolAddress((void**)&qkv_p, g_qkv);
    cudaGetSymbolAddress((void**)&y_p,   g_y);
    cudaGetSymbolAddress((void**)&x_p,   g_x);
    cudaGetSymbolAddress((void**)&wq_p,  g_wq);
    cudaGetSymbolAddress((void**)&wp_p,  g_wp);

    // 0) fp32 -> fp16 conversions
    f2h<<<(BT * D_MODEL) / 1024, 256>>>(x, x_p);
    f2h<<<(3 * D_MODEL * D_MODEL) / 1024, 256>>>(w_qkv, wq_p);
    f2h<<<(D_MODEL * D_MODEL) / 1024, 256>>>(w_proj, wp_p);

    // 1) qkv(fp16) = x @ w_qkv^T
    gemm_fp16<__half>
        <<<dim3(3 * D_MODEL / 128, BT / 128), 256>>>(x_p, wq_p, qkv_p,
                                                     BT, 3 * D_MODEL, D_MODEL);

    // 2) attention (fp16 in/out)
    attn_fp16<<<dim3(TT / 64, NH, BB), 128>>>();

    // 3) out(fp32) = y @ w_proj^T
    gemm_fp16<float>
        <<<dim3(D_MODEL / 128, BT / 128), 256>>>(y_p, wp_p, out,
                                                 BT, D_MODEL, D_MODEL);
}